// round 1
// baseline (speedup 1.0000x reference)
#include <cuda_runtime.h>
#include <math.h>

#define B_  2
#define S_  2048
#define E_  2048
#define H_  16
#define G_  4
#define HD_ 128
#define GD_ 512
#define MTOT (B_*S_)

// Scratch (device globals: allocation-free rule)
__device__ float g_Q[(size_t)B_*H_*S_*HD_];   // [b][h][s][d]
__device__ float g_K[(size_t)B_*G_*S_*HD_];   // [b][g][s][d]
__device__ float g_V[(size_t)B_*G_*S_*HD_];   // [b][g][s][d]
__device__ float g_O[(size_t)B_*S_*E_];       // [b][s][h*HD+d]

// ---------------------------------------------------------------------------
// GEMM: C = A[M,K] @ W[K,N] + bias.  BM=BN=128, BK=8, 256 thr, 8x8/thread.
// MODE 0: C row-major [M,N].
// MODE 1: head-split epilogue: col = head*HD+d -> C[((b*heads+head)*S+s)*HD+d]
//         (BN==HD so each block covers exactly one head)
// ---------------------------------------------------------------------------
template<int MODE>
__global__ __launch_bounds__(256)
void gemm_bias(const float* __restrict__ A, const float* __restrict__ W,
               const float* __restrict__ bias, float* __restrict__ C,
               int N, int K) {
    __shared__ __align__(16) float As[8][128];
    __shared__ __align__(16) float Bs[8][128];

    const int t  = threadIdx.x;
    const int tx = t & 15;
    const int ty = t >> 4;
    const int m0 = blockIdx.y * 128;
    const int n0 = blockIdx.x * 128;

    // A tile load: thread -> (row ar, 4 cols at ac4)
    const int ar  = t >> 1;
    const int ac4 = (t & 1) * 4;
    // B tile load: thread -> (row br, 4 cols at bc4)
    const int br  = t >> 5;
    const int bc4 = (t & 31) * 4;

    const float* Ap = A + (size_t)(m0 + ar) * K + ac4;
    const float* Bp = W + (size_t)br * N + n0 + bc4;

    float acc[8][8];
    #pragma unroll
    for (int i = 0; i < 8; i++)
        #pragma unroll
        for (int j = 0; j < 8; j++) acc[i][j] = 0.f;

    for (int k0 = 0; k0 < K; k0 += 8) {
        float4 a4 = *(const float4*)(Ap + k0);
        float4 b4 = *(const float4*)(Bp + (size_t)k0 * N);
        As[ac4+0][ar] = a4.x; As[ac4+1][ar] = a4.y;
        As[ac4+2][ar] = a4.z; As[ac4+3][ar] = a4.w;
        *(float4*)&Bs[br][bc4] = b4;
        __syncthreads();

        #pragma unroll
        for (int kk = 0; kk < 8; kk++) {
            float4 a0 = *(const float4*)&As[kk][ty*8];
            float4 a1 = *(const float4*)&As[kk][ty*8+4];
            float4 b0 = *(const float4*)&Bs[kk][tx*8];
            float4 b1 = *(const float4*)&Bs[kk][tx*8+4];
            float ra[8] = {a0.x,a0.y,a0.z,a0.w,a1.x,a1.y,a1.z,a1.w};
            float rb[8] = {b0.x,b0.y,b0.z,b0.w,b1.x,b1.y,b1.z,b1.w};
            #pragma unroll
            for (int i = 0; i < 8; i++)
                #pragma unroll
                for (int j = 0; j < 8; j++)
                    acc[i][j] = fmaf(ra[i], rb[j], acc[i][j]);
        }
        __syncthreads();
    }

    float bj[8];
    #pragma unroll
    for (int j = 0; j < 8; j++) bj[j] = bias[n0 + tx*8 + j];

    if (MODE == 0) {
        #pragma unroll
        for (int i = 0; i < 8; i++) {
            int row = m0 + ty*8 + i;
            float* Cp = C + (size_t)row * N + n0 + tx*8;
            #pragma unroll
            for (int j = 0; j < 8; j++) Cp[j] = acc[i][j] + bj[j];
        }
    } else {
        const int heads = N / HD_;      // BN == HD -> one head per block
        const int head  = n0 / HD_;
        #pragma unroll
        for (int i = 0; i < 8; i++) {
            int row = m0 + ty*8 + i;
            int bb = row / S_, ss = row % S_;
            float* Cp = C + (((size_t)(bb*heads + head))*S_ + ss)*HD_ + tx*8;
            #pragma unroll
            for (int j = 0; j < 8; j++) Cp[j] = acc[i][j] + bj[j];
        }
    }
}

// ---------------------------------------------------------------------------
// Flash attention (fp32, online softmax).
// Block = (qtile, h, b). 256 threads: row = t/4 (64 q rows), quad = t&3.
// Each thread owns output dims d = 4*(quad + 4*j4), j4=0..7 (float4 chunks)
// -> conflict-free SMEM V reads + coalesced global O stores.
// ---------------------------------------------------------------------------
#define QPAD 132   // 64x132 float tiles (528B rows, 16B aligned, bank-safe)
#define PPAD 68
#define FLASH_SMEM_BYTES ((3*64*QPAD + 64*PPAD)*4)

__global__ __launch_bounds__(256)
void flash_kernel(const int* __restrict__ mask, float* __restrict__ O) {
    extern __shared__ float sm[];
    float* Qs = sm;                    // 64 x QPAD
    float* Ks = Qs + 64*QPAD;
    float* Vs = Ks + 64*QPAD;
    float* Ps = Vs + 64*QPAD;          // 64 x PPAD

    const int t  = threadIdx.x;
    const int qt = blockIdx.x, h = blockIdx.y, b = blockIdx.z;
    const int g  = h % G_;             // tile(k,(1,NGH,1,1)) -> head h uses group h%G
    const int q0 = qt * 64;

    const float* Qg = g_Q + (((size_t)(b*H_ + h))*S_ + q0) * HD_;
    const float* Kg = g_K + (((size_t)(b*G_ + g))*S_) * HD_;
    const float* Vg = g_V + (((size_t)(b*G_ + g))*S_) * HD_;

    // Load Q tile (2048 float4s / 256 threads = 8 each)
    #pragma unroll
    for (int i = 0; i < 8; i++) {
        int f4 = i*256 + t;
        int r = f4 >> 5, c = (f4 & 31) << 2;
        *(float4*)(Qs + r*QPAD + c) = *(const float4*)(Qg + (size_t)r*HD_ + c);
    }

    const int row = t >> 2, quad = t & 3;
    const int* mbase = mask + ((size_t)b*S_ + (q0 + row)) * S_;

    float m = -1e30f, l = 0.f;
    float4 o4[8];
    #pragma unroll
    for (int j = 0; j < 8; j++) o4[j] = make_float4(0.f,0.f,0.f,0.f);

    for (int kt = 0; kt < S_/64; kt++) {
        __syncthreads();   // previous tile fully consumed (and Q ready on kt=0)
        #pragma unroll
        for (int i = 0; i < 8; i++) {
            int f4 = i*256 + t;
            int r = f4 >> 5, c = (f4 & 31) << 2;
            *(float4*)(Ks + r*QPAD + c) =
                *(const float4*)(Kg + ((size_t)(kt*64 + r))*HD_ + c);
            *(float4*)(Vs + r*QPAD + c) =
                *(const float4*)(Vg + ((size_t)(kt*64 + r))*HD_ + c);
        }
        __syncthreads();

        // ---- scores: thread computes kv = j*4 + quad, j=0..15 ----
        float s[16];
        #pragma unroll
        for (int j = 0; j < 16; j++) s[j] = 0.f;
        const float4* q4 = (const float4*)(Qs + row*QPAD);
        const float4* k4 = (const float4*)(Ks + quad*QPAD);   // +j*4*QPAD per j
        #pragma unroll
        for (int d = 0; d < 32; d++) {
            float4 qq = q4[d];
            #pragma unroll
            for (int j = 0; j < 16; j++) {
                float4 kk = k4[j*QPAD + d];   // (j*4+quad)*QPAD/4... QPAD words per row of 4
                s[j] = fmaf(qq.x, kk.x, s[j]);
                s[j] = fmaf(qq.y, kk.y, s[j]);
                s[j] = fmaf(qq.z, kk.z, s[j]);
                s[j] = fmaf(qq.w, kk.w, s[j]);
            }
        }
        #pragma unroll
        for (int j = 0; j < 16; j++) {
            float v = s[j] * 0.08838834764831845f;      // 1/sqrt(128)
            if (mbase[kt*64 + j*4 + quad] == 0) v = -10000.f;
            s[j] = v;
        }

        // ---- online softmax (4 lanes per row are consecutive in warp) ----
        float lm = s[0];
        #pragma unroll
        for (int j = 1; j < 16; j++) lm = fmaxf(lm, s[j]);
        lm = fmaxf(lm, __shfl_xor_sync(0xffffffffu, lm, 1));
        lm = fmaxf(lm, __shfl_xor_sync(0xffffffffu, lm, 2));
        float mn  = fmaxf(m, lm);
        float fac = __expf(m - mn);
        float psum = 0.f;
        #pragma unroll
        for (int j = 0; j < 16; j++) {
            float p = __expf(s[j] - mn);
            psum += p;
            Ps[row*PPAD + j*4 + quad] = p;
        }
        psum += __shfl_xor_sync(0xffffffffu, psum, 1);
        psum += __shfl_xor_sync(0xffffffffu, psum, 2);
        l = l * fac + psum;
        m = mn;
        #pragma unroll
        for (int j = 0; j < 8; j++) {
            o4[j].x *= fac; o4[j].y *= fac; o4[j].z *= fac; o4[j].w *= fac;
        }
        __syncwarp();   // Ps visible across the row's 4 lanes (same warp)

        // ---- AV: o[d] += p[kv] * V[kv][d], d4 = quad + 4*j4 (conflict-free) ----
        #pragma unroll 4
        for (int kv = 0; kv < 64; kv++) {
            float p = Ps[row*PPAD + kv];
            const float4* v4 = (const float4*)(Vs + kv*QPAD) + quad;
            #pragma unroll
            for (int j = 0; j < 8; j++) {
                float4 v = v4[4*j];
                o4[j].x = fmaf(p, v.x, o4[j].x);
                o4[j].y = fmaf(p, v.y, o4[j].y);
                o4[j].z = fmaf(p, v.z, o4[j].z);
                o4[j].w = fmaf(p, v.w, o4[j].w);
            }
        }
    }

    float inv = 1.f / l;
    float* Og = O + ((size_t)b*S_ + (q0 + row)) * E_ + h*HD_;
    #pragma unroll
    for (int j = 0; j < 8; j++) {
        float4 v = make_float4(o4[j].x*inv, o4[j].y*inv, o4[j].z*inv, o4[j].w*inv);
        *(float4*)(Og + 4*(quad + 4*j)) = v;
    }
}

// ---------------------------------------------------------------------------
extern "C" void kernel_launch(void* const* d_in, const int* in_sizes, int n_in,
                              void* d_out, int out_size) {
    const float* x  = (const float*)d_in[0];
    const int* mask = (const int*)  d_in[1];
    const float* Wq = (const float*)d_in[2];
    const float* bq = (const float*)d_in[3];
    const float* Wk = (const float*)d_in[4];
    const float* bk = (const float*)d_in[5];
    const float* Wv = (const float*)d_in[6];
    const float* bv = (const float*)d_in[7];
    const float* Wo = (const float*)d_in[8];
    const float* bo = (const float*)d_in[9];
    float* out = (float*)d_out;

    float *Qd, *Kd, *Vd, *Od;
    cudaGetSymbolAddress((void**)&Qd, g_Q);
    cudaGetSymbolAddress((void**)&Kd, g_K);
    cudaGetSymbolAddress((void**)&Vd, g_V);
    cudaGetSymbolAddress((void**)&Od, g_O);

    cudaFuncSetAttribute(flash_kernel,
                         cudaFuncAttributeMaxDynamicSharedMemorySize,
                         FLASH_SMEM_BYTES);

    // Q/K/V projections with head-split epilogue
    gemm_bias<1><<<dim3(E_/128,  MTOT/128), 256>>>(x, Wq, bq, Qd, E_,  E_);
    gemm_bias<1><<<dim3(GD_/128, MTOT/128), 256>>>(x, Wk, bk, Kd, GD_, E_);
    gemm_bias<1><<<dim3(GD_/128, MTOT/128), 256>>>(x, Wv, bv, Vd, GD_, E_);

    // Fused attention
    flash_kernel<<<dim3(S_/64, H_, B_), 256, FLASH_SMEM_BYTES>>>(mask, Od);

    // Output projection -> d_out
    gemm_bias<0><<<dim3(E_/128, MTOT/128), 256>>>(Od, Wo, bo, out, E_, E_);
}

// round 3
// speedup vs baseline: 1.2994x; 1.2994x over previous
#include <cuda_runtime.h>
#include <math.h>
#include <stdint.h>

#define B_  2
#define S_  2048
#define E_  2048
#define H_  16
#define G_  4
#define HD_ 128
#define GD_ 512
#define MTOT (B_*S_)

// ---------------- device scratch (allocation-free rule) ----------------
__device__ float g_Q [(size_t)B_*H_*S_*HD_];   // [b][h][s][d]
__device__ float g_K [(size_t)B_*G_*S_*HD_];   // [b][g][s][d]
__device__ float g_V [(size_t)B_*G_*S_*HD_];   // [b][g][s][d]
__device__ float g_O [(size_t)B_*S_*E_];       // attn out (tf32-rounded)
__device__ float g_Xr[(size_t)B_*S_*E_];       // x rounded to tf32
__device__ float g_WqT[(size_t)E_*E_];         // W^T [N][K], tf32-rounded
__device__ float g_WkT[(size_t)GD_*E_];
__device__ float g_WvT[(size_t)GD_*E_];
__device__ float g_WoT[(size_t)E_*E_];

// ---------------- helpers ----------------
__device__ __forceinline__ uint32_t smem_u32(const void* p) {
    uint32_t a;
    asm("{ .reg .u64 t; cvta.to.shared.u64 t, %1; cvt.u32.u64 %0, t; }" : "=r"(a) : "l"(p));
    return a;
}
__device__ __forceinline__ float rna_tf32(float x) {
    uint32_t u;
    asm("cvt.rna.tf32.f32 %0, %1;" : "=r"(u) : "f"(x));
    return __uint_as_float(u);
}

#define CP_ASYNC16(dst, src) \
    asm volatile("cp.async.cg.shared.global [%0], [%1], 16;" :: "r"(dst), "l"(src) : "memory")
#define CP_COMMIT() asm volatile("cp.async.commit_group;" ::: "memory")
#define CP_WAIT1()  asm volatile("cp.async.wait_group 1;"  ::: "memory")

__device__ __forceinline__ void mma_tf32(float& d0, float& d1, float& d2, float& d3,
                                         uint32_t a0, uint32_t a1, uint32_t a2, uint32_t a3,
                                         uint32_t b0, uint32_t b1) {
    asm volatile("mma.sync.aligned.m16n8k8.row.col.f32.tf32.tf32.f32 "
                 "{%0,%1,%2,%3},{%4,%5,%6,%7},{%8,%9},{%0,%1,%2,%3};"
                 : "+f"(d0), "+f"(d1), "+f"(d2), "+f"(d3)
                 : "r"(a0), "r"(a1), "r"(a2), "r"(a3), "r"(b0), "r"(b1));
}

// ---------------------------------------------------------------------------
// mma.sync tf32 GEMM: C[M,N] = A[M,K] @ WT[N,K]^T + bias
// 128x128x32 tile/CTA, 256 thr (warps 4M x 2N, warp tile 32x64), 3-stage cp.async.
// SMEM: A/B stored [row][k] with PAD=36 words -> conflict-free fragment LDS.
// MODE 0: row-major store. MODE 1: head-split store (N-tile == HD == 128).
// ---------------------------------------------------------------------------
#define PAD 36
#define STG_WORDS (128*PAD)                    // per matrix per stage
#define STG_BYTES (2*STG_WORDS*4)              // A+B per stage = 36864
#define GEMM_SMEM (3*STG_BYTES)                // 110592

template<int MODE>
__global__ __launch_bounds__(256)
void gemm_mma(const float* __restrict__ A, const float* __restrict__ Bw,
              const float* __restrict__ bias, float* __restrict__ C,
              int N, int K) {
    extern __shared__ __align__(16) float sm[];
    const uint32_t smb = smem_u32(sm);

    const int t    = threadIdx.x;
    const int lane = t & 31;
    const int wid  = t >> 5;
    const int wm   = wid & 3;          // 4 warps in M
    const int wn   = wid >> 2;         // 2 warps in N
    const int gq   = lane >> 2;        // group 0..7
    const int tr   = lane & 3;         // 0..3
    const int m0 = blockIdx.y * 128, n0 = blockIdx.x * 128;

    // loader mapping: 1024 float4 per matrix per stage, 4 per thread
    const int lrow = t >> 1;                 // rows 0..127 (2 thr/row)
    const int lc4a = (t & 1) * 4;            // plus i*8 cols
    const float* Ag = A  + (size_t)(m0 + lrow) * K;
    const float* Bg = Bw + (size_t)(n0 + lrow) * K;
    const uint32_t sArow = smb + (uint32_t)(lrow*PAD + lc4a) * 4;
    const uint32_t sBrow = sArow + STG_WORDS*4;

    float acc[2][8][4];
    #pragma unroll
    for (int i = 0; i < 2; i++)
        #pragma unroll
        for (int j = 0; j < 8; j++)
            #pragma unroll
            for (int r = 0; r < 4; r++) acc[i][j][r] = 0.f;

    const int KT = K >> 5;   // K/32

    // prologue: stages 0,1
    #pragma unroll
    for (int p = 0; p < 2; p++) {
        const int k0 = p * 32;
        #pragma unroll
        for (int i = 0; i < 4; i++) {   // i covers cols lc4a + {0,8,16,24}
            int c = lc4a + i*8;
            CP_ASYNC16(sArow + (uint32_t)(p*STG_BYTES) + i*8*4, Ag + k0 + c);
            CP_ASYNC16(sBrow + (uint32_t)(p*STG_BYTES) + i*8*4, Bg + k0 + c);
        }
        CP_COMMIT();
    }

    int s = 0, sl = 2;   // compute stage, load stage
    for (int it = 0; it < KT; it++) {
        CP_WAIT1();
        __syncthreads();

        if (it + 2 < KT) {
            const int k0 = (it + 2) * 32;
            const uint32_t so = (uint32_t)(sl * STG_BYTES);
            #pragma unroll
            for (int i = 0; i < 4; i++) {
                int c = lc4a + i*8;
                CP_ASYNC16(sArow + so + i*8*4, Ag + k0 + c);
                CP_ASYNC16(sBrow + so + i*8*4, Bg + k0 + c);
            }
        }
        CP_COMMIT();

        // ---- compute stage s ----
        const float* sA = sm + s * (STG_BYTES/4);
        const float* sB = sA + STG_WORDS;
        #pragma unroll
        for (int ks = 0; ks < 4; ks++) {
            const int kc = ks*8 + tr;
            uint32_t a[2][4];
            #pragma unroll
            for (int mf = 0; mf < 2; mf++) {
                const float* p0 = sA + (wm*32 + mf*16 + gq)*PAD + kc;
                a[mf][0] = __float_as_uint(p0[0]);
                a[mf][1] = __float_as_uint(p0[8*PAD]);
                a[mf][2] = __float_as_uint(p0[4]);
                a[mf][3] = __float_as_uint(p0[8*PAD + 4]);
            }
            #pragma unroll
            for (int nf = 0; nf < 8; nf++) {
                const float* p0 = sB + (wn*64 + nf*8 + gq)*PAD + kc;
                uint32_t b0 = __float_as_uint(p0[0]);
                uint32_t b1 = __float_as_uint(p0[4]);
                #pragma unroll
                for (int mf = 0; mf < 2; mf++)
                    mma_tf32(acc[mf][nf][0], acc[mf][nf][1], acc[mf][nf][2], acc[mf][nf][3],
                             a[mf][0], a[mf][1], a[mf][2], a[mf][3], b0, b1);
            }
        }

        s = (s + 1 == 3) ? 0 : s + 1;
        sl = (sl + 1 == 3) ? 0 : sl + 1;
    }

    // ---- epilogue ----
    #pragma unroll
    for (int mf = 0; mf < 2; mf++) {
        const int row0 = m0 + wm*32 + mf*16 + gq;
        #pragma unroll
        for (int nf = 0; nf < 8; nf++) {
            const int col = n0 + wn*64 + nf*8 + tr*2;
            const float b0 = bias[col], b1 = bias[col+1];
            float* Cp0; float* Cp1;
            if (MODE == 0) {
                Cp0 = C + (size_t)row0 * N + col;
                Cp1 = Cp0 + (size_t)8 * N;
            } else {
                const int heads = N >> 7, head = n0 >> 7;
                const int bb0 = row0 / S_, ss0 = row0 % S_;
                const int r1 = row0 + 8;
                const int bb1 = r1 / S_,  ss1 = r1 % S_;
                const int dcol = (col - n0);
                Cp0 = C + (((size_t)(bb0*heads + head))*S_ + ss0)*HD_ + dcol;
                Cp1 = C + (((size_t)(bb1*heads + head))*S_ + ss1)*HD_ + dcol;
            }
            *(float2*)Cp0 = make_float2(acc[mf][nf][0] + b0, acc[mf][nf][1] + b1);
            *(float2*)Cp1 = make_float2(acc[mf][nf][2] + b0, acc[mf][nf][3] + b1);
        }
    }
}

// ---------------------------------------------------------------------------
// Prep: tf32 round copy, transpose+round (W[K,N] -> WT[N,K])
// ---------------------------------------------------------------------------
__global__ void round_copy(const float* __restrict__ in, float* __restrict__ out, int n) {
    int i = blockIdx.x * 256 + threadIdx.x;
    if (i < n) out[i] = rna_tf32(in[i]);
}

__global__ void transpose_rna(const float* __restrict__ in, float* __restrict__ out,
                              int R, int Ccols) {   // in[R][Ccols] -> out[Ccols][R]
    __shared__ float tt[32][33];
    const int c0 = blockIdx.x * 32, r0 = blockIdx.y * 32;
    const int x = threadIdx.x, y = threadIdx.y;     // block (32,8)
    #pragma unroll
    for (int i = y; i < 32; i += 8)
        tt[i][x] = in[(size_t)(r0 + i) * Ccols + c0 + x];
    __syncthreads();
    #pragma unroll
    for (int i = y; i < 32; i += 8)
        out[(size_t)(c0 + i) * R + r0 + x] = rna_tf32(tt[x][i]);
}

// ---------------------------------------------------------------------------
// Flash attention (fp32, online softmax) — unchanged from R1 except tf32 store
// ---------------------------------------------------------------------------
#define QPAD 132
#define PPAD 68
#define FLASH_SMEM_BYTES ((3*64*QPAD + 64*PPAD)*4)

__global__ __launch_bounds__(256)
void flash_kernel(const int* __restrict__ mask, float* __restrict__ O) {
    extern __shared__ float fsm[];
    float* Qs = fsm;
    float* Ks = Qs + 64*QPAD;
    float* Vs = Ks + 64*QPAD;
    float* Ps = Vs + 64*QPAD;

    const int t  = threadIdx.x;
    const int qt = blockIdx.x, h = blockIdx.y, b = blockIdx.z;
    const int g  = h % G_;
    const int q0 = qt * 64;

    const float* Qg = g_Q + (((size_t)(b*H_ + h))*S_ + q0) * HD_;
    const float* Kg = g_K + (((size_t)(b*G_ + g))*S_) * HD_;
    const float* Vg = g_V + (((size_t)(b*G_ + g))*S_) * HD_;

    #pragma unroll
    for (int i = 0; i < 8; i++) {
        int f4 = i*256 + t;
        int r = f4 >> 5, c = (f4 & 31) << 2;
        *(float4*)(Qs + r*QPAD + c) = *(const float4*)(Qg + (size_t)r*HD_ + c);
    }

    const int row = t >> 2, quad = t & 3;
    const int* mbase = mask + ((size_t)b*S_ + (q0 + row)) * S_;

    float m = -1e30f, l = 0.f;
    float4 o4[8];
    #pragma unroll
    for (int j = 0; j < 8; j++) o4[j] = make_float4(0.f,0.f,0.f,0.f);

    for (int kt = 0; kt < S_/64; kt++) {
        __syncthreads();
        #pragma unroll
        for (int i = 0; i < 8; i++) {
            int f4 = i*256 + t;
            int r = f4 >> 5, c = (f4 & 31) << 2;
            *(float4*)(Ks + r*QPAD + c) = *(const float4*)(Kg + ((size_t)(kt*64 + r))*HD_ + c);
            *(float4*)(Vs + r*QPAD + c) = *(const float4*)(Vg + ((size_t)(kt*64 + r))*HD_ + c);
        }
        __syncthreads();

        float s[16];
        #pragma unroll
        for (int j = 0; j < 16; j++) s[j] = 0.f;
        const float4* q4 = (const float4*)(Qs + row*QPAD);
        const float4* k4 = (const float4*)(Ks + quad*QPAD);
        #pragma unroll
        for (int d = 0; d < 32; d++) {
            float4 qq = q4[d];
            #pragma unroll
            for (int j = 0; j < 16; j++) {
                float4 kk = k4[j*QPAD + d];
                s[j] = fmaf(qq.x, kk.x, s[j]);
                s[j] = fmaf(qq.y, kk.y, s[j]);
                s[j] = fmaf(qq.z, kk.z, s[j]);
                s[j] = fmaf(qq.w, kk.w, s[j]);
            }
        }
        #pragma unroll
        for (int j = 0; j < 16; j++) {
            float v = s[j] * 0.08838834764831845f;
            if (mbase[kt*64 + j*4 + quad] == 0) v = -10000.f;
            s[j] = v;
        }

        float lm = s[0];
        #pragma unroll
        for (int j = 1; j < 16; j++) lm = fmaxf(lm, s[j]);
        lm = fmaxf(lm, __shfl_xor_sync(0xffffffffu, lm, 1));
        lm = fmaxf(lm, __shfl_xor_sync(0xffffffffu, lm, 2));
        float mn  = fmaxf(m, lm);
        float fac = __expf(m - mn);
        float psum = 0.f;
        #pragma unroll
        for (int j = 0; j < 16; j++) {
            float p = __expf(s[j] - mn);
            psum += p;
            Ps[row*PPAD + j*4 + quad] = p;
        }
        psum += __shfl_xor_sync(0xffffffffu, psum, 1);
        psum += __shfl_xor_sync(0xffffffffu, psum, 2);
        l = l * fac + psum;
        m = mn;
        #pragma unroll
        for (int j = 0; j < 8; j++) {
            o4[j].x *= fac; o4[j].y *= fac; o4[j].z *= fac; o4[j].w *= fac;
        }
        __syncwarp();

        #pragma unroll 4
        for (int kv = 0; kv < 64; kv++) {
            float p = Ps[row*PPAD + kv];
            const float4* v4 = (const float4*)(Vs + kv*QPAD) + quad;
            #pragma unroll
            for (int j = 0; j < 8; j++) {
                float4 v = v4[4*j];
                o4[j].x = fmaf(p, v.x, o4[j].x);
                o4[j].y = fmaf(p, v.y, o4[j].y);
                o4[j].z = fmaf(p, v.z, o4[j].z);
                o4[j].w = fmaf(p, v.w, o4[j].w);
            }
        }
    }

    float inv = 1.f / l;
    float* Og = O + ((size_t)b*S_ + (q0 + row)) * E_ + h*HD_;
    #pragma unroll
    for (int j = 0; j < 8; j++) {
        float4 v = make_float4(rna_tf32(o4[j].x*inv), rna_tf32(o4[j].y*inv),
                               rna_tf32(o4[j].z*inv), rna_tf32(o4[j].w*inv));
        *(float4*)(Og + 4*(quad + 4*j)) = v;
    }
}

// ---------------------------------------------------------------------------
extern "C" void kernel_launch(void* const* d_in, const int* in_sizes, int n_in,
                              void* d_out, int out_size) {
    const float* x  = (const float*)d_in[0];
    const int* mask = (const int*)  d_in[1];
    const float* Wq = (const float*)d_in[2];
    const float* bq = (const float*)d_in[3];
    const float* Wk = (const float*)d_in[4];
    const float* bk = (const float*)d_in[5];
    const float* Wv = (const float*)d_in[6];
    const float* bv = (const float*)d_in[7];
    const float* Wo = (const float*)d_in[8];
    const float* bo = (const float*)d_in[9];
    float* out = (float*)d_out;

    float *Qd,*Kd,*Vd,*Od,*Xr,*WqT,*WkT,*WvT,*WoT;
    cudaGetSymbolAddress((void**)&Qd,  g_Q);
    cudaGetSymbolAddress((void**)&Kd,  g_K);
    cudaGetSymbolAddress((void**)&Vd,  g_V);
    cudaGetSymbolAddress((void**)&Od,  g_O);
    cudaGetSymbolAddress((void**)&Xr,  g_Xr);
    cudaGetSymbolAddress((void**)&WqT, g_WqT);
    cudaGetSymbolAddress((void**)&WkT, g_WkT);
    cudaGetSymbolAddress((void**)&WvT, g_WvT);
    cudaGetSymbolAddress((void**)&WoT, g_WoT);

    cudaFuncSetAttribute(flash_kernel, cudaFuncAttributeMaxDynamicSharedMemorySize, FLASH_SMEM_BYTES);
    cudaFuncSetAttribute(gemm_mma<0>,  cudaFuncAttributeMaxDynamicSharedMemorySize, GEMM_SMEM);
    cudaFuncSetAttribute(gemm_mma<1>,  cudaFuncAttributeMaxDynamicSharedMemorySize, GEMM_SMEM);

    // prep: tf32 rounding + weight transposes
    round_copy<<<(MTOT*E_ + 255)/256, 256>>>(x, Xr, MTOT*E_);
    transpose_rna<<<dim3(E_/32,  E_/32), dim3(32,8)>>>(Wq, WqT, E_, E_);
    transpose_rna<<<dim3(GD_/32, E_/32), dim3(32,8)>>>(Wk, WkT, E_, GD_);
    transpose_rna<<<dim3(GD_/32, E_/32), dim3(32,8)>>>(Wv, WvT, E_, GD_);
    transpose_rna<<<dim3(E_/32,  E_/32), dim3(32,8)>>>(Wo, WoT, E_, E_);

    // projections (mma.sync tf32)
    gemm_mma<1><<<dim3(E_/128,  MTOT/128), 256, GEMM_SMEM>>>(Xr, WqT, bq, Qd, E_,  E_);
    gemm_mma<1><<<dim3(GD_/128, MTOT/128), 256, GEMM_SMEM>>>(Xr, WkT, bk, Kd, GD_, E_);
    gemm_mma<1><<<dim3(GD_/128, MTOT/128), 256, GEMM_SMEM>>>(Xr, WvT, bv, Vd, GD_, E_);

    // attention (fp32 flash)
    flash_kernel<<<dim3(S_/64, H_, B_), 256, FLASH_SMEM_BYTES>>>(mask, Od);

    // output projection
    gemm_mma<0><<<dim3(E_/128, MTOT/128), 256, GEMM_SMEM>>>(Od, WoT, bo, out, E_, E_);
}

// round 5
// speedup vs baseline: 4.1622x; 3.2032x over previous
#include <cuda_runtime.h>
#include <math.h>
#include <stdint.h>

#define B_  2
#define S_  2048
#define E_  2048
#define H_  16
#define G_  4
#define HD_ 128
#define GD_ 512
#define MTOT (B_*S_)

// ---------------- device scratch (allocation-free rule) ----------------
__device__ float g_Q [(size_t)B_*H_*S_*HD_];   // [b][h][s][d]   (tf32-rounded)
__device__ float g_K [(size_t)B_*G_*S_*HD_];   // [b][g][s][d]   (tf32-rounded)
__device__ float g_V [(size_t)B_*G_*S_*HD_];   // [b][g][s][d]   (tf32-rounded)
__device__ float g_Vt[(size_t)B_*G_*HD_*S_];   // [b][g][d][s]   (transposed V)
__device__ float g_O [(size_t)B_*S_*E_];       // attn out (tf32-rounded)
__device__ float g_Xr[(size_t)B_*S_*E_];       // x rounded to tf32
__device__ float g_WqT[(size_t)E_*E_];         // W^T [N][K], tf32-rounded
__device__ float g_WkT[(size_t)GD_*E_];
__device__ float g_WvT[(size_t)GD_*E_];
__device__ float g_WoT[(size_t)E_*E_];

// ---------------- helpers ----------------
__device__ __forceinline__ uint32_t smem_u32(const void* p) {
    uint32_t a;
    asm("{ .reg .u64 t; cvta.to.shared.u64 t, %1; cvt.u32.u64 %0, t; }" : "=r"(a) : "l"(p));
    return a;
}
__device__ __forceinline__ float rna_tf32(float x) {
    uint32_t u;
    asm("cvt.rna.tf32.f32 %0, %1;" : "=r"(u) : "f"(x));
    return __uint_as_float(u);
}

#define CP_ASYNC16(dst, src) \
    asm volatile("cp.async.cg.shared.global [%0], [%1], 16;" :: "r"(dst), "l"(src) : "memory")
#define CP_COMMIT() asm volatile("cp.async.commit_group;" ::: "memory")
#define CP_WAIT1()  asm volatile("cp.async.wait_group 1;"  ::: "memory")

__device__ __forceinline__ void mma_tf32(float& d0, float& d1, float& d2, float& d3,
                                         uint32_t a0, uint32_t a1, uint32_t a2, uint32_t a3,
                                         uint32_t b0, uint32_t b1) {
    asm volatile("mma.sync.aligned.m16n8k8.row.col.f32.tf32.tf32.f32 "
                 "{%0,%1,%2,%3},{%4,%5,%6,%7},{%8,%9},{%0,%1,%2,%3};"
                 : "+f"(d0), "+f"(d1), "+f"(d2), "+f"(d3)
                 : "r"(a0), "r"(a1), "r"(a2), "r"(a3), "r"(b0), "r"(b1));
}
#define FU(x) __float_as_uint(x)

// ---------------------------------------------------------------------------
// mma.sync tf32 GEMM (identical to R3/R4 passing version).
// ---------------------------------------------------------------------------
#define PAD 36
#define STG_WORDS (128*PAD)
#define STG_BYTES (2*STG_WORDS*4)
#define GEMM_SMEM (3*STG_BYTES)

template<int MODE>
__global__ __launch_bounds__(256)
void gemm_mma(const float* __restrict__ A, const float* __restrict__ Bw,
              const float* __restrict__ bias, float* __restrict__ C,
              int N, int K) {
    extern __shared__ __align__(16) float sm[];

    const int t    = threadIdx.x;
    const int lane = t & 31;
    const int wid  = t >> 5;
    const int wm   = wid & 3;
    const int wn   = wid >> 2;
    const int gq   = lane >> 2;
    const int tr   = lane & 3;
    const int m0 = blockIdx.y * 128, n0 = blockIdx.x * 128;

    const int lrow = t >> 1;
    const int lc4a = (t & 1) * 4;
    const float* Ag = A  + (size_t)(m0 + lrow) * K;
    const float* Bg = Bw + (size_t)(n0 + lrow) * K;
    const uint32_t smb = smem_u32(sm);
    const uint32_t sArow = smb + (uint32_t)(lrow*PAD + lc4a) * 4;
    const uint32_t sBrow = sArow + STG_WORDS*4;

    float acc[2][8][4];
    #pragma unroll
    for (int i = 0; i < 2; i++)
        #pragma unroll
        for (int j = 0; j < 8; j++)
            #pragma unroll
            for (int r = 0; r < 4; r++) acc[i][j][r] = 0.f;

    const int KT = K >> 5;

    #pragma unroll
    for (int p = 0; p < 2; p++) {
        const int k0 = p * 32;
        #pragma unroll
        for (int i = 0; i < 4; i++) {
            int c = lc4a + i*8;
            CP_ASYNC16(sArow + (uint32_t)(p*STG_BYTES) + i*8*4, Ag + k0 + c);
            CP_ASYNC16(sBrow + (uint32_t)(p*STG_BYTES) + i*8*4, Bg + k0 + c);
        }
        CP_COMMIT();
    }

    int s = 0, sl = 2;
    for (int it = 0; it < KT; it++) {
        CP_WAIT1();
        __syncthreads();

        if (it + 2 < KT) {
            const int k0 = (it + 2) * 32;
            const uint32_t so = (uint32_t)(sl * STG_BYTES);
            #pragma unroll
            for (int i = 0; i < 4; i++) {
                int c = lc4a + i*8;
                CP_ASYNC16(sArow + so + i*8*4, Ag + k0 + c);
                CP_ASYNC16(sBrow + so + i*8*4, Bg + k0 + c);
            }
        }
        CP_COMMIT();

        const float* sA = sm + s * (STG_BYTES/4);
        const float* sB = sA + STG_WORDS;
        #pragma unroll
        for (int ks = 0; ks < 4; ks++) {
            const int kc = ks*8 + tr;
            uint32_t a[2][4];
            #pragma unroll
            for (int mf = 0; mf < 2; mf++) {
                const float* p0 = sA + (wm*32 + mf*16 + gq)*PAD + kc;
                a[mf][0] = __float_as_uint(p0[0]);
                a[mf][1] = __float_as_uint(p0[8*PAD]);
                a[mf][2] = __float_as_uint(p0[4]);
                a[mf][3] = __float_as_uint(p0[8*PAD + 4]);
            }
            #pragma unroll
            for (int nf = 0; nf < 8; nf++) {
                const float* p0 = sB + (wn*64 + nf*8 + gq)*PAD + kc;
                uint32_t b0 = __float_as_uint(p0[0]);
                uint32_t b1 = __float_as_uint(p0[4]);
                #pragma unroll
                for (int mf = 0; mf < 2; mf++)
                    mma_tf32(acc[mf][nf][0], acc[mf][nf][1], acc[mf][nf][2], acc[mf][nf][3],
                             a[mf][0], a[mf][1], a[mf][2], a[mf][3], b0, b1);
            }
        }

        s = (s + 1 == 3) ? 0 : s + 1;
        sl = (sl + 1 == 3) ? 0 : sl + 1;
    }

    #pragma unroll
    for (int mf = 0; mf < 2; mf++) {
        const int row0 = m0 + wm*32 + mf*16 + gq;
        #pragma unroll
        for (int nf = 0; nf < 8; nf++) {
            const int col = n0 + wn*64 + nf*8 + tr*2;
            const float b0 = bias[col], b1 = bias[col+1];
            if (MODE == 0) {
                float* Cp0 = C + (size_t)row0 * N + col;
                float* Cp1 = Cp0 + (size_t)8 * N;
                *(float2*)Cp0 = make_float2(acc[mf][nf][0] + b0, acc[mf][nf][1] + b1);
                *(float2*)Cp1 = make_float2(acc[mf][nf][2] + b0, acc[mf][nf][3] + b1);
            } else {
                const int heads = N >> 7, head = n0 >> 7;
                const int bb0 = row0 / S_, ss0 = row0 % S_;
                const int r1 = row0 + 8;
                const int bb1 = r1 / S_,  ss1 = r1 % S_;
                const int dcol = (col - n0);
                float* Cp0 = C + (((size_t)(bb0*heads + head))*S_ + ss0)*HD_ + dcol;
                float* Cp1 = C + (((size_t)(bb1*heads + head))*S_ + ss1)*HD_ + dcol;
                *(float2*)Cp0 = make_float2(rna_tf32(acc[mf][nf][0] + b0), rna_tf32(acc[mf][nf][1] + b1));
                *(float2*)Cp1 = make_float2(rna_tf32(acc[mf][nf][2] + b0), rna_tf32(acc[mf][nf][3] + b1));
            }
        }
    }
}

// ---------------------------------------------------------------------------
// Prep kernels
// ---------------------------------------------------------------------------
__global__ void round_copy(const float* __restrict__ in, float* __restrict__ out, int n) {
    int i = blockIdx.x * 256 + threadIdx.x;
    if (i < n) out[i] = rna_tf32(in[i]);
}

__global__ void transpose_rna(const float* __restrict__ in, float* __restrict__ out,
                              int R, int Ccols) {   // in[R][Ccols] -> out[Ccols][R]
    __shared__ float tt[32][33];
    const int c0 = blockIdx.x * 32, r0 = blockIdx.y * 32;
    const int x = threadIdx.x, y = threadIdx.y;
    #pragma unroll
    for (int i = y; i < 32; i += 8)
        tt[i][x] = in[(size_t)(r0 + i) * Ccols + c0 + x];
    __syncthreads();
    #pragma unroll
    for (int i = y; i < 32; i += 8)
        out[(size_t)(c0 + i) * R + r0 + x] = rna_tf32(tt[x][i]);
}

// batched V transpose: per z slice, in[S][HD] -> out[HD][S]
__global__ void vtrans(const float* __restrict__ in, float* __restrict__ out) {
    __shared__ float tt[32][33];
    const int z = blockIdx.z;
    const float* ip = in  + (size_t)z*S_*HD_;
    float*       op = out + (size_t)z*S_*HD_;
    const int s0 = blockIdx.x * 32, d0 = blockIdx.y * 32;
    const int x = threadIdx.x, y = threadIdx.y;
    #pragma unroll
    for (int i = y; i < 32; i += 8)
        tt[i][x] = ip[(size_t)(s0 + i)*HD_ + d0 + x];
    __syncthreads();
    #pragma unroll
    for (int i = y; i < 32; i += 8)
        op[(size_t)(d0 + i)*S_ + s0 + x] = tt[x][i];
}

// ---------------------------------------------------------------------------
// Flash attention with mma.sync tf32.
// CTA: 128 q-rows x one (b,h). 8 warps, warp = 16 q-rows. kv tile = 64.
// K smem tile [64][132]; V^T smem tile [128][68]; 2-stage cp.async.
// FIXED (R5): full tile loads — 8 float4 per thread per matrix per tile.
// ---------------------------------------------------------------------------
#define KTILE_W 8448            // 64*132 floats per K stage
#define VTILE_W 8704            // 128*68 floats per V stage
#define KSTG_B  (KTILE_W*4)     // 33792
#define VSTG_B  (VTILE_W*4)     // 34816
#define FLASH_SMEM (2*KSTG_B + 2*VSTG_B)   // 137216

__global__ __launch_bounds__(256, 1)
void flash_mma(const int* __restrict__ mask, float* __restrict__ O) {
    extern __shared__ __align__(16) float fsm[];
    const int t = threadIdx.x, lane = t & 31, w = t >> 5;
    const int gq = lane >> 2, tr = lane & 3;
    const int qt = blockIdx.x, h = blockIdx.y, b = blockIdx.z;
    const int g  = h % G_;
    const int q0 = qt * 128;

    const float* Qg  = g_Q  + (((size_t)(b*H_ + h))*S_ + q0) * HD_;
    const float* Kg  = g_K  + (((size_t)(b*G_ + g))*S_) * HD_;
    const float* Vtg = g_Vt + (((size_t)(b*G_ + g))*HD_) * S_;

    const uint32_t uK = smem_u32(fsm);
    const uint32_t uV = uK + 2*KSTG_B;

    // loader coords: K rows (t>>5)+8i, col (t&31)*4; V rows (t>>4)+16i, col (t&15)*4
    const int krow = t >> 5,  kcol = (t & 31) * 4;
    const int vrow = t >> 4,  vcol = (t & 15) * 4;

    // ---- Q fragments: 16 k-steps x 4 regs, scaled + tf32-rounded ----
    const float scale = 0.08838834764831845f;
    const int qrow = w*16 + gq;
    float qa[16][4];
    #pragma unroll
    for (int ks = 0; ks < 16; ks++) {
        const int c = ks*8 + tr;
        qa[ks][0] = rna_tf32(__ldg(Qg + (size_t)qrow*HD_ + c) * scale);
        qa[ks][1] = rna_tf32(__ldg(Qg + (size_t)(qrow+8)*HD_ + c) * scale);
        qa[ks][2] = rna_tf32(__ldg(Qg + (size_t)qrow*HD_ + c + 4) * scale);
        qa[ks][3] = rna_tf32(__ldg(Qg + (size_t)(qrow+8)*HD_ + c + 4) * scale);
    }

    float oc[16][4];
    #pragma unroll
    for (int jf = 0; jf < 16; jf++)
        #pragma unroll
        for (int r = 0; r < 4; r++) oc[jf][r] = 0.f;
    float m0 = -1e30f, m1 = -1e30f, l0 = 0.f, l1 = 0.f;

    // prologue: tile 0 -> stage 0
    #pragma unroll
    for (int i = 0; i < 8; i++) {
        CP_ASYNC16(uK + (uint32_t)((krow + i*8)*132 + kcol)*4,
                   Kg + (size_t)(krow + i*8)*HD_ + kcol);
        CP_ASYNC16(uV + (uint32_t)((vrow + i*16)*68 + vcol)*4,
                   Vtg + (size_t)(vrow + i*16)*S_ + vcol);
    }
    CP_COMMIT();

    const size_t mrow0 = ((size_t)(b*S_ + q0 + w*16 + gq)) * S_;
    const size_t mrow1 = mrow0 + (size_t)8 * S_;
    const unsigned sl0 = (unsigned)((lane & 28) | (tr >> 1));
    const unsigned sl1 = sl0 | 2u;
    const bool odd = (tr & 1);

    for (int kt = 0; kt < S_/64; kt++) {
        __syncthreads();     // all warps done reading the buffer we're about to overwrite
        if (kt + 1 < S_/64) {
            const uint32_t so = ((kt+1) & 1);
            const size_t kvo = (size_t)(kt+1) * 64;
            #pragma unroll
            for (int i = 0; i < 8; i++) {
                CP_ASYNC16(uK + so*KSTG_B + (uint32_t)((krow + i*8)*132 + kcol)*4,
                           Kg + (kvo + krow + i*8)*HD_ + kcol);
                CP_ASYNC16(uV + so*VSTG_B + (uint32_t)((vrow + i*16)*68 + vcol)*4,
                           Vtg + (size_t)(vrow + i*16)*S_ + kvo + vcol);
            }
        }
        CP_COMMIT();
        CP_WAIT1();
        __syncthreads();     // tile kt visible to all warps

        const float* Kt = fsm + (kt & 1) * KTILE_W;
        const float* Vt = fsm + 2*KTILE_W + (kt & 1) * VTILE_W;

        // ---- scores S = Q K^T  (8 n-frags of 8 cols) ----
        float sc[8][4];
        #pragma unroll
        for (int j = 0; j < 8; j++)
            #pragma unroll
            for (int r = 0; r < 4; r++) sc[j][r] = 0.f;
        #pragma unroll
        for (int ks = 0; ks < 16; ks++) {
            const float* kp = Kt + gq*132 + ks*8 + tr;
            #pragma unroll
            for (int j = 0; j < 8; j++) {
                const float b0 = kp[j*8*132];
                const float b1 = kp[j*8*132 + 4];
                mma_tf32(sc[j][0], sc[j][1], sc[j][2], sc[j][3],
                         FU(qa[ks][0]), FU(qa[ks][1]), FU(qa[ks][2]), FU(qa[ks][3]),
                         FU(b0), FU(b1));
            }
        }

        // ---- mask + row max ----
        const int mc = kt*64 + tr*2;
        float mx0 = -1e30f, mx1 = -1e30f;
        #pragma unroll
        for (int j = 0; j < 8; j++) {
            int2 mA = *(const int2*)(mask + mrow0 + mc + j*8);
            int2 mB = *(const int2*)(mask + mrow1 + mc + j*8);
            if (mA.x == 0) sc[j][0] = -10000.f;
            if (mA.y == 0) sc[j][1] = -10000.f;
            if (mB.x == 0) sc[j][2] = -10000.f;
            if (mB.y == 0) sc[j][3] = -10000.f;
            mx0 = fmaxf(mx0, fmaxf(sc[j][0], sc[j][1]));
            mx1 = fmaxf(mx1, fmaxf(sc[j][2], sc[j][3]));
        }
        mx0 = fmaxf(mx0, __shfl_xor_sync(0xffffffffu, mx0, 1));
        mx0 = fmaxf(mx0, __shfl_xor_sync(0xffffffffu, mx0, 2));
        mx1 = fmaxf(mx1, __shfl_xor_sync(0xffffffffu, mx1, 1));
        mx1 = fmaxf(mx1, __shfl_xor_sync(0xffffffffu, mx1, 2));

        const float mn0 = fmaxf(m0, mx0), mn1 = fmaxf(m1, mx1);
        const float f0 = __expf(m0 - mn0), f1 = __expf(m1 - mn1);
        m0 = mn0; m1 = mn1;

        float s0 = 0.f, s1 = 0.f;
        #pragma unroll
        for (int j = 0; j < 8; j++) {
            sc[j][0] = __expf(sc[j][0] - mn0); s0 += sc[j][0];
            sc[j][1] = __expf(sc[j][1] - mn0); s0 += sc[j][1];
            sc[j][2] = __expf(sc[j][2] - mn1); s1 += sc[j][2];
            sc[j][3] = __expf(sc[j][3] - mn1); s1 += sc[j][3];
        }
        s0 += __shfl_xor_sync(0xffffffffu, s0, 1);
        s0 += __shfl_xor_sync(0xffffffffu, s0, 2);
        s1 += __shfl_xor_sync(0xffffffffu, s1, 1);
        s1 += __shfl_xor_sync(0xffffffffu, s1, 2);
        l0 = l0 * f0 + s0;
        l1 = l1 * f1 + s1;

        #pragma unroll
        for (int jf = 0; jf < 16; jf++) {
            oc[jf][0] *= f0; oc[jf][1] *= f0;
            oc[jf][2] *= f1; oc[jf][3] *= f1;
        }

        // ---- PV: convert P frag ks on the fly, then 16 d-frags of mma ----
        #pragma unroll
        for (int ks = 0; ks < 8; ks++) {
            const float q00 = __shfl_sync(0xffffffffu, sc[ks][0], sl0);
            const float q01 = __shfl_sync(0xffffffffu, sc[ks][1], sl0);
            const float q10 = __shfl_sync(0xffffffffu, sc[ks][0], sl1);
            const float q11 = __shfl_sync(0xffffffffu, sc[ks][1], sl1);
            const float r00 = __shfl_sync(0xffffffffu, sc[ks][2], sl0);
            const float r01 = __shfl_sync(0xffffffffu, sc[ks][3], sl0);
            const float r10 = __shfl_sync(0xffffffffu, sc[ks][2], sl1);
            const float r11 = __shfl_sync(0xffffffffu, sc[ks][3], sl1);
            const uint32_t a0 = FU(rna_tf32(odd ? q01 : q00));
            const uint32_t a2 = FU(rna_tf32(odd ? q11 : q10));
            const uint32_t a1 = FU(rna_tf32(odd ? r01 : r00));
            const uint32_t a3 = FU(rna_tf32(odd ? r11 : r10));
            const float* vp = Vt + gq*68 + ks*8 + tr;
            #pragma unroll
            for (int jf = 0; jf < 16; jf++) {
                const float b0 = vp[jf*8*68];
                const float b1 = vp[jf*8*68 + 4];
                mma_tf32(oc[jf][0], oc[jf][1], oc[jf][2], oc[jf][3],
                         a0, a1, a2, a3, FU(b0), FU(b1));
            }
        }
    }

    // ---- epilogue ----
    const float inv0 = 1.f / l0, inv1 = 1.f / l1;
    float* O0 = O + ((size_t)(b*S_ + q0 + w*16 + gq)) * E_ + h*HD_;
    float* O1 = O0 + (size_t)8 * E_;
    #pragma unroll
    for (int jf = 0; jf < 16; jf++) {
        const int c = jf*8 + tr*2;
        *(float2*)(O0 + c) = make_float2(rna_tf32(oc[jf][0]*inv0), rna_tf32(oc[jf][1]*inv0));
        *(float2*)(O1 + c) = make_float2(rna_tf32(oc[jf][2]*inv1), rna_tf32(oc[jf][3]*inv1));
    }
}

// ---------------------------------------------------------------------------
extern "C" void kernel_launch(void* const* d_in, const int* in_sizes, int n_in,
                              void* d_out, int out_size) {
    const float* x  = (const float*)d_in[0];
    const int* mask = (const int*)  d_in[1];
    const float* Wq = (const float*)d_in[2];
    const float* bq = (const float*)d_in[3];
    const float* Wk = (const float*)d_in[4];
    const float* bk = (const float*)d_in[5];
    const float* Wv = (const float*)d_in[6];
    const float* bv = (const float*)d_in[7];
    const float* Wo = (const float*)d_in[8];
    const float* bo = (const float*)d_in[9];
    float* out = (float*)d_out;

    float *Qd,*Kd,*Vd,*Vtd,*Od,*Xr,*WqT,*WkT,*WvT,*WoT;
    cudaGetSymbolAddress((void**)&Qd,  g_Q);
    cudaGetSymbolAddress((void**)&Kd,  g_K);
    cudaGetSymbolAddress((void**)&Vd,  g_V);
    cudaGetSymbolAddress((void**)&Vtd, g_Vt);
    cudaGetSymbolAddress((void**)&Od,  g_O);
    cudaGetSymbolAddress((void**)&Xr,  g_Xr);
    cudaGetSymbolAddress((void**)&WqT, g_WqT);
    cudaGetSymbolAddress((void**)&WkT, g_WkT);
    cudaGetSymbolAddress((void**)&WvT, g_WvT);
    cudaGetSymbolAddress((void**)&WoT, g_WoT);

    cudaFuncSetAttribute(flash_mma,   cudaFuncAttributeMaxDynamicSharedMemorySize, FLASH_SMEM);
    cudaFuncSetAttribute(gemm_mma<0>, cudaFuncAttributeMaxDynamicSharedMemorySize, GEMM_SMEM);
    cudaFuncSetAttribute(gemm_mma<1>, cudaFuncAttributeMaxDynamicSharedMemorySize, GEMM_SMEM);

    // prep: tf32 rounding + weight transposes
    round_copy<<<(MTOT*E_ + 255)/256, 256>>>(x, Xr, MTOT*E_);
    transpose_rna<<<dim3(E_/32,  E_/32), dim3(32,8)>>>(Wq, WqT, E_, E_);
    transpose_rna<<<dim3(GD_/32, E_/32), dim3(32,8)>>>(Wk, WkT, E_, GD_);
    transpose_rna<<<dim3(GD_/32, E_/32), dim3(32,8)>>>(Wv, WvT, E_, GD_);
    transpose_rna<<<dim3(E_/32,  E_/32), dim3(32,8)>>>(Wo, WoT, E_, E_);

    // projections (mma.sync tf32), epilogue rounds Q/K/V
    gemm_mma<1><<<dim3(E_/128,  MTOT/128), 256, GEMM_SMEM>>>(Xr, WqT, bq, Qd, E_,  E_);
    gemm_mma<1><<<dim3(GD_/128, MTOT/128), 256, GEMM_SMEM>>>(Xr, WkT, bk, Kd, GD_, E_);
    gemm_mma<1><<<dim3(GD_/128, MTOT/128), 256, GEMM_SMEM>>>(Xr, WvT, bv, Vd, GD_, E_);

    // V transpose: [b][g][s][d] -> [b][g][d][s]
    vtrans<<<dim3(S_/32, HD_/32, B_*G_), dim3(32,8)>>>(Vd, Vtd);

    // attention (mma.sync tf32 flash)
    flash_mma<<<dim3(S_/128, H_, B_), 256, FLASH_SMEM>>>(mask, Od);

    // output projection
    gemm_mma<0><<<dim3(E_/128, MTOT/128), 256, GEMM_SMEM>>>(Od, WoT, bo, out, E_, E_);
}

// round 6
// speedup vs baseline: 8.2598x; 1.9845x over previous
#include <cuda_runtime.h>
#include <cuda_fp16.h>
#include <math.h>
#include <stdint.h>

#define B_  2
#define S_  2048
#define E_  2048
#define H_  16
#define G_  4
#define HD_ 128
#define GD_ 512
#define MTOT (B_*S_)

// ---------------- device scratch (allocation-free rule) ----------------
__device__ __half g_Q [(size_t)B_*H_*S_*HD_];   // [b][h][s][d]
__device__ __half g_K [(size_t)B_*G_*S_*HD_];   // [b][g][s][d]
__device__ __half g_V [(size_t)B_*G_*S_*HD_];   // [b][g][s][d]
__device__ __half g_Vt[(size_t)B_*G_*HD_*S_];   // [b][g][d][s]
__device__ __half g_O [(size_t)B_*S_*E_];       // attn out
__device__ __half g_Xr[(size_t)B_*S_*E_];       // x in fp16
__device__ __half g_WqT[(size_t)E_*E_];         // W^T [N][K] fp16
__device__ __half g_WkT[(size_t)GD_*E_];
__device__ __half g_WvT[(size_t)GD_*E_];
__device__ __half g_WoT[(size_t)E_*E_];

// ---------------- helpers ----------------
__device__ __forceinline__ uint32_t smem_u32(const void* p) {
    uint32_t a;
    asm("{ .reg .u64 t; cvta.to.shared.u64 t, %1; cvt.u32.u64 %0, t; }" : "=r"(a) : "l"(p));
    return a;
}
__device__ __forceinline__ uint32_t pack_h2(float lo, float hi) {
    __half2 v = __floats2half2_rn(lo, hi);
    return *reinterpret_cast<uint32_t*>(&v);
}

#define CP_ASYNC16(dst, src) \
    asm volatile("cp.async.cg.shared.global [%0], [%1], 16;" :: "r"(dst), "l"(src) : "memory")
#define CP_COMMIT() asm volatile("cp.async.commit_group;" ::: "memory")
#define CP_WAIT1()  asm volatile("cp.async.wait_group 1;"  ::: "memory")

__device__ __forceinline__ void mma_f16(float& d0, float& d1, float& d2, float& d3,
                                        uint32_t a0, uint32_t a1, uint32_t a2, uint32_t a3,
                                        uint32_t b0, uint32_t b1) {
    asm volatile("mma.sync.aligned.m16n8k16.row.col.f32.f16.f16.f32 "
                 "{%0,%1,%2,%3},{%4,%5,%6,%7},{%8,%9},{%0,%1,%2,%3};"
                 : "+f"(d0), "+f"(d1), "+f"(d2), "+f"(d3)
                 : "r"(a0), "r"(a1), "r"(a2), "r"(a3), "r"(b0), "r"(b1));
}

// ---------------------------------------------------------------------------
// fp16 mma GEMM: C[M,N] = A[M,K] @ WT[N,K]^T + bias.
// 128x128 tile/CTA, BK=64 halves, 3-stage cp.async, 256 thr (4Mx2N warps).
// SMEM rows: 64 halves + 8 pad = 72 halves (144B, 36 words == 4 mod 32).
// MODE 0: float row-major out. MODE 1: half head-split out (N-tile == HD).
// ---------------------------------------------------------------------------
#define GROW_H 72
#define GSTG_B (128*GROW_H*2)        // 18432 per matrix per stage
#define GSTG_PAIR (2*GSTG_B)         // 36864
#define GEMM_SMEM (3*GSTG_PAIR)      // 110592

template<int MODE>
__global__ __launch_bounds__(256)
void gemm_h(const __half* __restrict__ A, const __half* __restrict__ Bw,
            const float* __restrict__ bias, void* __restrict__ Cv,
            int N, int K) {
    extern __shared__ __align__(16) unsigned char gsm[];
    const uint32_t smb = smem_u32(gsm);

    const int t    = threadIdx.x;
    const int lane = t & 31;
    const int wid  = t >> 5;
    const int wm   = wid & 3;
    const int wn   = wid >> 2;
    const int gq   = lane >> 2;
    const int tr   = lane & 3;
    const int m0 = blockIdx.y * 128, n0 = blockIdx.x * 128;

    // loader: 8 threads/row, rows row8+32i (i<4), 16B chunk = chk
    const int row8 = t >> 3, chk = t & 7;
    const __half* Agr = A  + (size_t)(m0 + row8) * K + chk*8;
    const __half* Bgr = Bw + (size_t)(n0 + row8) * K + chk*8;
    const uint32_t dA = smb + (uint32_t)(row8*144 + chk*16);
    const uint32_t dB = dA + GSTG_B;

    float acc[2][8][4];
    #pragma unroll
    for (int i = 0; i < 2; i++)
        #pragma unroll
        for (int j = 0; j < 8; j++)
            #pragma unroll
            for (int r = 0; r < 4; r++) acc[i][j][r] = 0.f;

    const int KT = K >> 6;   // K/64 = 32

    #pragma unroll
    for (int p = 0; p < 2; p++) {
        const int k0 = p * 64;
        #pragma unroll
        for (int i = 0; i < 4; i++) {
            CP_ASYNC16(dA + p*GSTG_PAIR + i*32*144, Agr + (size_t)(i*32)*K + k0);
            CP_ASYNC16(dB + p*GSTG_PAIR + i*32*144, Bgr + (size_t)(i*32)*K + k0);
        }
        CP_COMMIT();
    }

    int s = 0, sl = 2;
    for (int it = 0; it < KT; it++) {
        CP_WAIT1();
        __syncthreads();

        if (it + 2 < KT) {
            const int k0 = (it + 2) * 64;
            const uint32_t so = (uint32_t)(sl * GSTG_PAIR);
            #pragma unroll
            for (int i = 0; i < 4; i++) {
                CP_ASYNC16(dA + so + i*32*144, Agr + (size_t)(i*32)*K + k0);
                CP_ASYNC16(dB + so + i*32*144, Bgr + (size_t)(i*32)*K + k0);
            }
        }
        CP_COMMIT();

        const __half* sA = (const __half*)(gsm + s*GSTG_PAIR);
        const __half* sB = (const __half*)(gsm + s*GSTG_PAIR + GSTG_B);
        #pragma unroll
        for (int ks = 0; ks < 4; ks++) {
            const int kc = ks*16 + tr*2;
            uint32_t a[2][4];
            #pragma unroll
            for (int mf = 0; mf < 2; mf++) {
                const __half* p0 = sA + (wm*32 + mf*16 + gq)*GROW_H + kc;
                a[mf][0] = *(const uint32_t*)(p0);
                a[mf][1] = *(const uint32_t*)(p0 + 8*GROW_H);
                a[mf][2] = *(const uint32_t*)(p0 + 8);
                a[mf][3] = *(const uint32_t*)(p0 + 8*GROW_H + 8);
            }
            #pragma unroll
            for (int nf = 0; nf < 8; nf++) {
                const __half* p0 = sB + (wn*64 + nf*8 + gq)*GROW_H + kc;
                const uint32_t b0 = *(const uint32_t*)(p0);
                const uint32_t b1 = *(const uint32_t*)(p0 + 8);
                #pragma unroll
                for (int mf = 0; mf < 2; mf++)
                    mma_f16(acc[mf][nf][0], acc[mf][nf][1], acc[mf][nf][2], acc[mf][nf][3],
                            a[mf][0], a[mf][1], a[mf][2], a[mf][3], b0, b1);
            }
        }

        s = (s + 1 == 3) ? 0 : s + 1;
        sl = (sl + 1 == 3) ? 0 : sl + 1;
    }

    #pragma unroll
    for (int mf = 0; mf < 2; mf++) {
        const int row0 = m0 + wm*32 + mf*16 + gq;
        #pragma unroll
        for (int nf = 0; nf < 8; nf++) {
            const int col = n0 + wn*64 + nf*8 + tr*2;
            const float b0 = bias[col], b1 = bias[col+1];
            if (MODE == 0) {
                float* C = (float*)Cv;
                float* Cp0 = C + (size_t)row0 * N + col;
                float* Cp1 = Cp0 + (size_t)8 * N;
                *(float2*)Cp0 = make_float2(acc[mf][nf][0] + b0, acc[mf][nf][1] + b1);
                *(float2*)Cp1 = make_float2(acc[mf][nf][2] + b0, acc[mf][nf][3] + b1);
            } else {
                __half* C = (__half*)Cv;
                const int heads = N >> 7, head = n0 >> 7;
                const int bb0 = row0 / S_, ss0 = row0 % S_;
                const int r1 = row0 + 8;
                const int bb1 = r1 / S_,  ss1 = r1 % S_;
                const int dcol = (col - n0);
                __half* Cp0 = C + (((size_t)(bb0*heads + head))*S_ + ss0)*HD_ + dcol;
                __half* Cp1 = C + (((size_t)(bb1*heads + head))*S_ + ss1)*HD_ + dcol;
                *(uint32_t*)Cp0 = pack_h2(acc[mf][nf][0] + b0, acc[mf][nf][1] + b1);
                *(uint32_t*)Cp1 = pack_h2(acc[mf][nf][2] + b0, acc[mf][nf][3] + b1);
            }
        }
    }
}

// ---------------------------------------------------------------------------
// Prep kernels
// ---------------------------------------------------------------------------
__global__ void f2h_copy(const float* __restrict__ in, __half* __restrict__ out, int n2) {
    int i = blockIdx.x * 256 + threadIdx.x;   // i indexes pairs
    if (i < n2) {
        float2 v = *(const float2*)(in + 2*i);
        *(uint32_t*)(out + 2*i) = pack_h2(v.x, v.y);
    }
}

__global__ void transpose_h(const float* __restrict__ in, __half* __restrict__ out,
                            int R, int Ccols) {   // in[R][Ccols] -> out[Ccols][R] fp16
    __shared__ float tt[32][33];
    const int c0 = blockIdx.x * 32, r0 = blockIdx.y * 32;
    const int x = threadIdx.x, y = threadIdx.y;     // block (32,8)
    #pragma unroll
    for (int i = y; i < 32; i += 8)
        tt[i][x] = in[(size_t)(r0 + i) * Ccols + c0 + x];
    __syncthreads();
    #pragma unroll
    for (int i = y; i < 32; i += 8)
        out[(size_t)(c0 + i) * R + r0 + x] = __float2half_rn(tt[x][i]);
}

// batched V transpose (half): per z slice, in[S][HD] -> out[HD][S]
__global__ void vtrans_h(const __half* __restrict__ in, __half* __restrict__ out) {
    __shared__ __half tt[32][34];
    const int z = blockIdx.z;
    const __half* ip = in  + (size_t)z*S_*HD_;
    __half*       op = out + (size_t)z*S_*HD_;
    const int s0 = blockIdx.x * 32, d0 = blockIdx.y * 32;
    const int x = threadIdx.x, y = threadIdx.y;
    #pragma unroll
    for (int i = y; i < 32; i += 8)
        tt[i][x] = ip[(size_t)(s0 + i)*HD_ + d0 + x];
    __syncthreads();
    #pragma unroll
    for (int i = y; i < 32; i += 8)
        op[(size_t)(d0 + i)*S_ + s0 + x] = tt[x][i];
}

// ---------------------------------------------------------------------------
// Flash attention with fp16 mma (m16n8k16).
// CTA: 128 q-rows x one (b,h). 8 warps x 16 rows. kv tile 64, 2-stage.
// K tile [64][136h] (272B rows); V^T tile [128][72h] (144B rows).
// Q frags persist (scaled, fp16). P->A frag is pure local half2 packing.
// ---------------------------------------------------------------------------
#define FKROW_H 136
#define FVROW_H 72
#define FKSTG_B (64*FKROW_H*2)     // 17408
#define FVSTG_B (128*FVROW_H*2)    // 18432
#define FLASH_SMEM (2*FKSTG_B + 2*FVSTG_B)   // 71680

__global__ __launch_bounds__(256, 1)
void flash_h(const int* __restrict__ mask, __half* __restrict__ O) {
    extern __shared__ __align__(16) unsigned char fsm[];
    const int t = threadIdx.x, lane = t & 31, w = t >> 5;
    const int gq = lane >> 2, tr = lane & 3;
    const int qt = blockIdx.x, h = blockIdx.y, b = blockIdx.z;
    const int g  = h % G_;
    const int q0 = qt * 128;

    const __half* Qg  = g_Q  + (((size_t)(b*H_ + h))*S_ + q0) * HD_;
    const __half* Kg  = g_K  + (((size_t)(b*G_ + g))*S_) * HD_;
    const __half* Vtg = g_Vt + (((size_t)(b*G_ + g))*HD_) * S_;

    const uint32_t uK = smem_u32(fsm);
    const uint32_t uV = uK + 2*FKSTG_B;

    // loaders: 8 thr/row, 16B chunks
    const int row8 = t >> 3, chk = t & 7;

    // ---- Q fragments: 8 k16-steps x 4 regs (half2), scaled ----
    const float scale = 0.08838834764831845f;
    const int qrow = w*16 + gq;
    uint32_t qa[8][4];
    #pragma unroll
    for (int ks = 0; ks < 8; ks++) {
        const int c = ks*16 + tr*2;
        #pragma unroll
        for (int r = 0; r < 4; r++) {
            const int rr = qrow + (r & 1)*8;
            const int cc = c + (r >> 1)*8;
            const uint32_t u = *(const uint32_t*)(Qg + (size_t)rr*HD_ + cc);
            const __half2 hv = *reinterpret_cast<const __half2*>(&u);
            const float2 f = __half22float2(hv);
            qa[ks][r] = pack_h2(f.x*scale, f.y*scale);
        }
    }

    float oc[16][4];
    #pragma unroll
    for (int jf = 0; jf < 16; jf++)
        #pragma unroll
        for (int r = 0; r < 4; r++) oc[jf][r] = 0.f;
    float m0 = -1e30f, m1 = -1e30f, l0 = 0.f, l1 = 0.f;

    // prologue: tile 0 -> stage 0
    #pragma unroll
    for (int i = 0; i < 2; i++)      // K: rows row8+32i, chunks chk & chk+8
        #pragma unroll
        for (int c = 0; c < 2; c++)
            CP_ASYNC16(uK + (uint32_t)((row8 + 32*i)*272 + (chk + 8*c)*16),
                       Kg + (size_t)(row8 + 32*i)*HD_ + (chk + 8*c)*8);
    #pragma unroll
    for (int i = 0; i < 4; i++)      // V: rows row8+32i, chunk chk
        CP_ASYNC16(uV + (uint32_t)((row8 + 32*i)*144 + chk*16),
                   Vtg + (size_t)(row8 + 32*i)*S_ + chk*8);
    CP_COMMIT();

    const size_t mrow0 = ((size_t)(b*S_ + q0 + w*16 + gq)) * S_;
    const size_t mrow1 = mrow0 + (size_t)8 * S_;

    for (int kt = 0; kt < S_/64; kt++) {
        __syncthreads();
        if (kt + 1 < S_/64) {
            const uint32_t so = ((kt+1) & 1);
            const size_t kvo = (size_t)(kt+1) * 64;
            #pragma unroll
            for (int i = 0; i < 2; i++)
                #pragma unroll
                for (int c = 0; c < 2; c++)
                    CP_ASYNC16(uK + so*FKSTG_B + (uint32_t)((row8 + 32*i)*272 + (chk + 8*c)*16),
                               Kg + (kvo + row8 + 32*i)*HD_ + (chk + 8*c)*8);
            #pragma unroll
            for (int i = 0; i < 4; i++)
                CP_ASYNC16(uV + so*FVSTG_B + (uint32_t)((row8 + 32*i)*144 + chk*16),
                           Vtg + (size_t)(row8 + 32*i)*S_ + kvo + chk*8);
        }
        CP_COMMIT();
        CP_WAIT1();
        __syncthreads();

        const __half* Kt = (const __half*)(fsm + (kt & 1)*FKSTG_B);
        const __half* Vt = (const __half*)(fsm + 2*FKSTG_B + (kt & 1)*FVSTG_B);

        // ---- scores S = Q K^T : 8 n-frags ----
        float sc[8][4];
        #pragma unroll
        for (int j = 0; j < 8; j++)
            #pragma unroll
            for (int r = 0; r < 4; r++) sc[j][r] = 0.f;
        #pragma unroll
        for (int ks = 0; ks < 8; ks++) {
            const int kc = ks*16 + tr*2;
            #pragma unroll
            for (int j = 0; j < 8; j++) {
                const __half* kp = Kt + (j*8 + gq)*FKROW_H + kc;
                const uint32_t b0 = *(const uint32_t*)(kp);
                const uint32_t b1 = *(const uint32_t*)(kp + 8);
                mma_f16(sc[j][0], sc[j][1], sc[j][2], sc[j][3],
                        qa[ks][0], qa[ks][1], qa[ks][2], qa[ks][3], b0, b1);
            }
        }

        // ---- mask + row max ----
        const int mc = kt*64 + tr*2;
        float mx0 = -1e30f, mx1 = -1e30f;
        #pragma unroll
        for (int j = 0; j < 8; j++) {
            int2 mA = *(const int2*)(mask + mrow0 + mc + j*8);
            int2 mB = *(const int2*)(mask + mrow1 + mc + j*8);
            if (mA.x == 0) sc[j][0] = -10000.f;
            if (mA.y == 0) sc[j][1] = -10000.f;
            if (mB.x == 0) sc[j][2] = -10000.f;
            if (mB.y == 0) sc[j][3] = -10000.f;
            mx0 = fmaxf(mx0, fmaxf(sc[j][0], sc[j][1]));
            mx1 = fmaxf(mx1, fmaxf(sc[j][2], sc[j][3]));
        }
        mx0 = fmaxf(mx0, __shfl_xor_sync(0xffffffffu, mx0, 1));
        mx0 = fmaxf(mx0, __shfl_xor_sync(0xffffffffu, mx0, 2));
        mx1 = fmaxf(mx1, __shfl_xor_sync(0xffffffffu, mx1, 1));
        mx1 = fmaxf(mx1, __shfl_xor_sync(0xffffffffu, mx1, 2));

        const float mn0 = fmaxf(m0, mx0), mn1 = fmaxf(m1, mx1);
        const float f0 = __expf(m0 - mn0), f1 = __expf(m1 - mn1);
        m0 = mn0; m1 = mn1;

        float s0 = 0.f, s1 = 0.f;
        #pragma unroll
        for (int j = 0; j < 8; j++) {
            sc[j][0] = __expf(sc[j][0] - mn0); s0 += sc[j][0];
            sc[j][1] = __expf(sc[j][1] - mn0); s0 += sc[j][1];
            sc[j][2] = __expf(sc[j][2] - mn1); s1 += sc[j][2];
            sc[j][3] = __expf(sc[j][3] - mn1); s1 += sc[j][3];
        }
        s0 += __shfl_xor_sync(0xffffffffu, s0, 1);
        s0 += __shfl_xor_sync(0xffffffffu, s0, 2);
        s1 += __shfl_xor_sync(0xffffffffu, s1, 1);
        s1 += __shfl_xor_sync(0xffffffffu, s1, 2);
        l0 = l0 * f0 + s0;
        l1 = l1 * f1 + s1;

        #pragma unroll
        for (int jf = 0; jf < 16; jf++) {
            oc[jf][0] *= f0; oc[jf][1] *= f0;
            oc[jf][2] *= f1; oc[jf][3] *= f1;
        }

        // ---- PV: P A-frags are local accumulator packs (no shuffles) ----
        #pragma unroll
        for (int ks = 0; ks < 4; ks++) {
            const uint32_t a0 = pack_h2(sc[2*ks][0],   sc[2*ks][1]);
            const uint32_t a1 = pack_h2(sc[2*ks][2],   sc[2*ks][3]);
            const uint32_t a2 = pack_h2(sc[2*ks+1][0], sc[2*ks+1][1]);
            const uint32_t a3 = pack_h2(sc[2*ks+1][2], sc[2*ks+1][3]);
            const int kc = ks*16 + tr*2;
            #pragma unroll
            for (int jf = 0; jf < 16; jf++) {
                const __half* vp = Vt + (jf*8 + gq)*FVROW_H + kc;
                const uint32_t b0 = *(const uint32_t*)(vp);
                const uint32_t b1 = *(const uint32_t*)(vp + 8);
                mma_f16(oc[jf][0], oc[jf][1], oc[jf][2], oc[jf][3],
                        a0, a1, a2, a3, b0, b1);
            }
        }
    }

    // ---- epilogue (half2 stores into g_O) ----
    const float inv0 = 1.f / l0, inv1 = 1.f / l1;
    __half* O0 = O + ((size_t)(b*S_ + q0 + w*16 + gq)) * E_ + h*HD_;
    __half* O1 = O0 + (size_t)8 * E_;
    #pragma unroll
    for (int jf = 0; jf < 16; jf++) {
        const int c = jf*8 + tr*2;
        *(uint32_t*)(O0 + c) = pack_h2(oc[jf][0]*inv0, oc[jf][1]*inv0);
        *(uint32_t*)(O1 + c) = pack_h2(oc[jf][2]*inv1, oc[jf][3]*inv1);
    }
}

// ---------------------------------------------------------------------------
extern "C" void kernel_launch(void* const* d_in, const int* in_sizes, int n_in,
                              void* d_out, int out_size) {
    const float* x  = (const float*)d_in[0];
    const int* mask = (const int*)  d_in[1];
    const float* Wq = (const float*)d_in[2];
    const float* bq = (const float*)d_in[3];
    const float* Wk = (const float*)d_in[4];
    const float* bk = (const float*)d_in[5];
    const float* Wv = (const float*)d_in[6];
    const float* bv = (const float*)d_in[7];
    const float* Wo = (const float*)d_in[8];
    const float* bo = (const float*)d_in[9];
    float* out = (float*)d_out;

    __half *Qd,*Kd,*Vd,*Vtd,*Od,*Xr,*WqT,*WkT,*WvT,*WoT;
    cudaGetSymbolAddress((void**)&Qd,  g_Q);
    cudaGetSymbolAddress((void**)&Kd,  g_K);
    cudaGetSymbolAddress((void**)&Vd,  g_V);
    cudaGetSymbolAddress((void**)&Vtd, g_Vt);
    cudaGetSymbolAddress((void**)&Od,  g_O);
    cudaGetSymbolAddress((void**)&Xr,  g_Xr);
    cudaGetSymbolAddress((void**)&WqT, g_WqT);
    cudaGetSymbolAddress((void**)&WkT, g_WkT);
    cudaGetSymbolAddress((void**)&WvT, g_WvT);
    cudaGetSymbolAddress((void**)&WoT, g_WoT);

    cudaFuncSetAttribute(flash_h,   cudaFuncAttributeMaxDynamicSharedMemorySize, FLASH_SMEM);
    cudaFuncSetAttribute(gemm_h<0>, cudaFuncAttributeMaxDynamicSharedMemorySize, GEMM_SMEM);
    cudaFuncSetAttribute(gemm_h<1>, cudaFuncAttributeMaxDynamicSharedMemorySize, GEMM_SMEM);

    // prep: fp16 conversion + weight transposes
    f2h_copy<<<(MTOT*E_/2 + 255)/256, 256>>>(x, Xr, MTOT*E_/2);
    transpose_h<<<dim3(E_/32,  E_/32), dim3(32,8)>>>(Wq, WqT, E_, E_);
    transpose_h<<<dim3(GD_/32, E_/32), dim3(32,8)>>>(Wk, WkT, E_, GD_);
    transpose_h<<<dim3(GD_/32, E_/32), dim3(32,8)>>>(Wv, WvT, E_, GD_);
    transpose_h<<<dim3(E_/32,  E_/32), dim3(32,8)>>>(Wo, WoT, E_, E_);

    // projections (fp16 mma), epilogue writes half Q/K/V
    gemm_h<1><<<dim3(E_/128,  MTOT/128), 256, GEMM_SMEM>>>(Xr, WqT, bq, Qd, E_,  E_);
    gemm_h<1><<<dim3(GD_/128, MTOT/128), 256, GEMM_SMEM>>>(Xr, WkT, bk, Kd, GD_, E_);
    gemm_h<1><<<dim3(GD_/128, MTOT/128), 256, GEMM_SMEM>>>(Xr, WvT, bv, Vd, GD_, E_);

    // V transpose: [b][g][s][d] -> [b][g][d][s]
    vtrans_h<<<dim3(S_/32, HD_/32, B_*G_), dim3(32,8)>>>(Vd, Vtd);

    // attention (fp16 mma flash)
    flash_h<<<dim3(S_/128, H_, B_), 256, FLASH_SMEM>>>(mask, Od);

    // output projection -> fp32 out
    gemm_h<0><<<dim3(E_/128, MTOT/128), 256, GEMM_SMEM>>>(Od, WoT, bo, out, E_, E_);
}

// round 7
// speedup vs baseline: 9.0716x; 1.0983x over previous
#include <cuda_runtime.h>
#include <cuda_fp16.h>
#include <math.h>
#include <stdint.h>

#define B_  2
#define S_  2048
#define E_  2048
#define H_  16
#define G_  4
#define HD_ 128
#define GD_ 512
#define MTOT (B_*S_)

// ---------------- device scratch (allocation-free rule) ----------------
__device__ __half g_Q [(size_t)B_*H_*S_*HD_];   // [b][h][s][d]
__device__ __half g_K [(size_t)B_*G_*S_*HD_];   // [b][g][s][d]
__device__ __half g_V [(size_t)B_*G_*S_*HD_];   // [b][g][s][d]
__device__ __half g_Vt[(size_t)B_*G_*HD_*S_];   // [b][g][d][s]
__device__ __half g_O [(size_t)B_*S_*E_];       // attn out
__device__ __half g_Xr[(size_t)B_*S_*E_];       // x in fp16
__device__ __half g_WqT[(size_t)E_*E_];         // W^T [N][K] fp16
__device__ __half g_WkT[(size_t)GD_*E_];
__device__ __half g_WvT[(size_t)GD_*E_];
__device__ __half g_WoT[(size_t)E_*E_];

// ---------------- helpers ----------------
__device__ __forceinline__ uint32_t smem_u32(const void* p) {
    uint32_t a;
    asm("{ .reg .u64 t; cvta.to.shared.u64 t, %1; cvt.u32.u64 %0, t; }" : "=r"(a) : "l"(p));
    return a;
}
__device__ __forceinline__ uint32_t pack_h2(float lo, float hi) {
    __half2 v = __floats2half2_rn(lo, hi);
    return *reinterpret_cast<uint32_t*>(&v);
}

#define CP_ASYNC16(dst, src) \
    asm volatile("cp.async.cg.shared.global [%0], [%1], 16;" :: "r"(dst), "l"(src) : "memory")
#define CP_COMMIT() asm volatile("cp.async.commit_group;" ::: "memory")
#define CP_WAIT1()  asm volatile("cp.async.wait_group 1;"  ::: "memory")

__device__ __forceinline__ void mma_f16(float& d0, float& d1, float& d2, float& d3,
                                        uint32_t a0, uint32_t a1, uint32_t a2, uint32_t a3,
                                        uint32_t b0, uint32_t b1) {
    asm volatile("mma.sync.aligned.m16n8k16.row.col.f32.f16.f16.f32 "
                 "{%0,%1,%2,%3},{%4,%5,%6,%7},{%8,%9},{%0,%1,%2,%3};"
                 : "+f"(d0), "+f"(d1), "+f"(d2), "+f"(d3)
                 : "r"(a0), "r"(a1), "r"(a2), "r"(a3), "r"(b0), "r"(b1));
}

// ---------------------------------------------------------------------------
// fp16 mma GEMM: identical to R6 except __launch_bounds__(256, 2) -> 2 CTA/SM.
// ---------------------------------------------------------------------------
#define GROW_H 72
#define GSTG_B (128*GROW_H*2)        // 18432 per matrix per stage
#define GSTG_PAIR (2*GSTG_B)         // 36864
#define GEMM_SMEM (3*GSTG_PAIR)      // 110592  (2 per SM <= 227KB opt-in)

template<int MODE>
__global__ __launch_bounds__(256, 2)
void gemm_h(const __half* __restrict__ A, const __half* __restrict__ Bw,
            const float* __restrict__ bias, void* __restrict__ Cv,
            int N, int K) {
    extern __shared__ __align__(16) unsigned char gsm[];
    const uint32_t smb = smem_u32(gsm);

    const int t    = threadIdx.x;
    const int lane = t & 31;
    const int wid  = t >> 5;
    const int wm   = wid & 3;
    const int wn   = wid >> 2;
    const int gq   = lane >> 2;
    const int tr   = lane & 3;
    const int m0 = blockIdx.y * 128, n0 = blockIdx.x * 128;

    const int row8 = t >> 3, chk = t & 7;
    const __half* Agr = A  + (size_t)(m0 + row8) * K + chk*8;
    const __half* Bgr = Bw + (size_t)(n0 + row8) * K + chk*8;
    const uint32_t dA = smb + (uint32_t)(row8*144 + chk*16);
    const uint32_t dB = dA + GSTG_B;

    float acc[2][8][4];
    #pragma unroll
    for (int i = 0; i < 2; i++)
        #pragma unroll
        for (int j = 0; j < 8; j++)
            #pragma unroll
            for (int r = 0; r < 4; r++) acc[i][j][r] = 0.f;

    const int KT = K >> 6;

    #pragma unroll
    for (int p = 0; p < 2; p++) {
        const int k0 = p * 64;
        #pragma unroll
        for (int i = 0; i < 4; i++) {
            CP_ASYNC16(dA + p*GSTG_PAIR + i*32*144, Agr + (size_t)(i*32)*K + k0);
            CP_ASYNC16(dB + p*GSTG_PAIR + i*32*144, Bgr + (size_t)(i*32)*K + k0);
        }
        CP_COMMIT();
    }

    int s = 0, sl = 2;
    for (int it = 0; it < KT; it++) {
        CP_WAIT1();
        __syncthreads();

        if (it + 2 < KT) {
            const int k0 = (it + 2) * 64;
            const uint32_t so = (uint32_t)(sl * GSTG_PAIR);
            #pragma unroll
            for (int i = 0; i < 4; i++) {
                CP_ASYNC16(dA + so + i*32*144, Agr + (size_t)(i*32)*K + k0);
                CP_ASYNC16(dB + so + i*32*144, Bgr + (size_t)(i*32)*K + k0);
            }
        }
        CP_COMMIT();

        const __half* sA = (const __half*)(gsm + s*GSTG_PAIR);
        const __half* sB = (const __half*)(gsm + s*GSTG_PAIR + GSTG_B);
        #pragma unroll
        for (int ks = 0; ks < 4; ks++) {
            const int kc = ks*16 + tr*2;
            uint32_t a[2][4];
            #pragma unroll
            for (int mf = 0; mf < 2; mf++) {
                const __half* p0 = sA + (wm*32 + mf*16 + gq)*GROW_H + kc;
                a[mf][0] = *(const uint32_t*)(p0);
                a[mf][1] = *(const uint32_t*)(p0 + 8*GROW_H);
                a[mf][2] = *(const uint32_t*)(p0 + 8);
                a[mf][3] = *(const uint32_t*)(p0 + 8*GROW_H + 8);
            }
            #pragma unroll
            for (int nf = 0; nf < 8; nf++) {
                const __half* p0 = sB + (wn*64 + nf*8 + gq)*GROW_H + kc;
                const uint32_t b0 = *(const uint32_t*)(p0);
                const uint32_t b1 = *(const uint32_t*)(p0 + 8);
                #pragma unroll
                for (int mf = 0; mf < 2; mf++)
                    mma_f16(acc[mf][nf][0], acc[mf][nf][1], acc[mf][nf][2], acc[mf][nf][3],
                            a[mf][0], a[mf][1], a[mf][2], a[mf][3], b0, b1);
            }
        }

        s = (s + 1 == 3) ? 0 : s + 1;
        sl = (sl + 1 == 3) ? 0 : sl + 1;
    }

    #pragma unroll
    for (int mf = 0; mf < 2; mf++) {
        const int row0 = m0 + wm*32 + mf*16 + gq;
        #pragma unroll
        for (int nf = 0; nf < 8; nf++) {
            const int col = n0 + wn*64 + nf*8 + tr*2;
            const float b0 = bias[col], b1 = bias[col+1];
            if (MODE == 0) {
                float* C = (float*)Cv;
                float* Cp0 = C + (size_t)row0 * N + col;
                float* Cp1 = Cp0 + (size_t)8 * N;
                *(float2*)Cp0 = make_float2(acc[mf][nf][0] + b0, acc[mf][nf][1] + b1);
                *(float2*)Cp1 = make_float2(acc[mf][nf][2] + b0, acc[mf][nf][3] + b1);
            } else {
                __half* C = (__half*)Cv;
                const int heads = N >> 7, head = n0 >> 7;
                const int bb0 = row0 / S_, ss0 = row0 % S_;
                const int r1 = row0 + 8;
                const int bb1 = r1 / S_,  ss1 = r1 % S_;
                const int dcol = (col - n0);
                __half* Cp0 = C + (((size_t)(bb0*heads + head))*S_ + ss0)*HD_ + dcol;
                __half* Cp1 = C + (((size_t)(bb1*heads + head))*S_ + ss1)*HD_ + dcol;
                *(uint32_t*)Cp0 = pack_h2(acc[mf][nf][0] + b0, acc[mf][nf][1] + b1);
                *(uint32_t*)Cp1 = pack_h2(acc[mf][nf][2] + b0, acc[mf][nf][3] + b1);
            }
        }
    }
}

// ---------------------------------------------------------------------------
// Prep kernels (unchanged)
// ---------------------------------------------------------------------------
__global__ void f2h_copy(const float* __restrict__ in, __half* __restrict__ out, int n2) {
    int i = blockIdx.x * 256 + threadIdx.x;
    if (i < n2) {
        float2 v = *(const float2*)(in + 2*i);
        *(uint32_t*)(out + 2*i) = pack_h2(v.x, v.y);
    }
}

__global__ void transpose_h(const float* __restrict__ in, __half* __restrict__ out,
                            int R, int Ccols) {
    __shared__ float tt[32][33];
    const int c0 = blockIdx.x * 32, r0 = blockIdx.y * 32;
    const int x = threadIdx.x, y = threadIdx.y;
    #pragma unroll
    for (int i = y; i < 32; i += 8)
        tt[i][x] = in[(size_t)(r0 + i) * Ccols + c0 + x];
    __syncthreads();
    #pragma unroll
    for (int i = y; i < 32; i += 8)
        out[(size_t)(c0 + i) * R + r0 + x] = __float2half_rn(tt[x][i]);
}

__global__ void vtrans_h(const __half* __restrict__ in, __half* __restrict__ out) {
    __shared__ __half tt[32][34];
    const int z = blockIdx.z;
    const __half* ip = in  + (size_t)z*S_*HD_;
    __half*       op = out + (size_t)z*S_*HD_;
    const int s0 = blockIdx.x * 32, d0 = blockIdx.y * 32;
    const int x = threadIdx.x, y = threadIdx.y;
    #pragma unroll
    for (int i = y; i < 32; i += 8)
        tt[i][x] = ip[(size_t)(s0 + i)*HD_ + d0 + x];
    __syncthreads();
    #pragma unroll
    for (int i = y; i < 32; i += 8)
        op[(size_t)(d0 + i)*S_ + s0 + x] = tt[x][i];
}

// ---------------------------------------------------------------------------
// Flash attention fp16 mma — R7: 128-thread CTA, 64 q-rows, 2 CTAs/SM.
// 4 warps x 16 q-rows. kv tile 64, 2-stage. Tiles/smem identical to R6.
// ---------------------------------------------------------------------------
#define FKROW_H 136
#define FVROW_H 72
#define FKSTG_B (64*FKROW_H*2)     // 17408
#define FVSTG_B (128*FVROW_H*2)    // 18432
#define FLASH_SMEM (2*FKSTG_B + 2*FVSTG_B)   // 71680 (x2 per SM fits)

__global__ __launch_bounds__(128)
void flash_h(const int* __restrict__ mask, __half* __restrict__ O) {
    extern __shared__ __align__(16) unsigned char fsm[];
    const int t = threadIdx.x, lane = t & 31, w = t >> 5;   // w in 0..3
    const int gq = lane >> 2, tr = lane & 3;
    const int qt = blockIdx.x, h = blockIdx.y, b = blockIdx.z;
    const int g  = h % G_;
    const int q0 = qt * 64;

    const __half* Qg  = g_Q  + (((size_t)(b*H_ + h))*S_ + q0) * HD_;
    const __half* Kg  = g_K  + (((size_t)(b*G_ + g))*S_) * HD_;
    const __half* Vtg = g_Vt + (((size_t)(b*G_ + g))*HD_) * S_;

    const uint32_t uK = smem_u32(fsm);
    const uint32_t uV = uK + 2*FKSTG_B;

    // loaders (128 thr): K rows (t>>4)+8i i<8, chunk t&15 ; V rows (t>>3)+16i i<8, chunk t&7
    const int krow = t >> 4, kchk = t & 15;
    const int vrow = t >> 3, vchk = t & 7;

    // ---- Q fragments ----
    const float scale = 0.08838834764831845f;
    const int qrow = w*16 + gq;
    uint32_t qa[8][4];
    #pragma unroll
    for (int ks = 0; ks < 8; ks++) {
        const int c = ks*16 + tr*2;
        #pragma unroll
        for (int r = 0; r < 4; r++) {
            const int rr = qrow + (r & 1)*8;
            const int cc = c + (r >> 1)*8;
            const uint32_t u = *(const uint32_t*)(Qg + (size_t)rr*HD_ + cc);
            const __half2 hv = *reinterpret_cast<const __half2*>(&u);
            const float2 f = __half22float2(hv);
            qa[ks][r] = pack_h2(f.x*scale, f.y*scale);
        }
    }

    float oc[16][4];
    #pragma unroll
    for (int jf = 0; jf < 16; jf++)
        #pragma unroll
        for (int r = 0; r < 4; r++) oc[jf][r] = 0.f;
    float m0 = -1e30f, m1 = -1e30f, l0 = 0.f, l1 = 0.f;

    // prologue: tile 0 -> stage 0
    #pragma unroll
    for (int i = 0; i < 8; i++)
        CP_ASYNC16(uK + (uint32_t)((krow + 8*i)*272 + kchk*16),
                   Kg + (size_t)(krow + 8*i)*HD_ + kchk*8);
    #pragma unroll
    for (int i = 0; i < 8; i++)
        CP_ASYNC16(uV + (uint32_t)((vrow + 16*i)*144 + vchk*16),
                   Vtg + (size_t)(vrow + 16*i)*S_ + vchk*8);
    CP_COMMIT();

    const size_t mrow0 = ((size_t)(b*S_ + q0 + w*16 + gq)) * S_;
    const size_t mrow1 = mrow0 + (size_t)8 * S_;

    for (int kt = 0; kt < S_/64; kt++) {
        __syncthreads();
        if (kt + 1 < S_/64) {
            const uint32_t so = ((kt+1) & 1);
            const size_t kvo = (size_t)(kt+1) * 64;
            #pragma unroll
            for (int i = 0; i < 8; i++)
                CP_ASYNC16(uK + so*FKSTG_B + (uint32_t)((krow + 8*i)*272 + kchk*16),
                           Kg + (kvo + krow + 8*i)*HD_ + kchk*8);
            #pragma unroll
            for (int i = 0; i < 8; i++)
                CP_ASYNC16(uV + so*FVSTG_B + (uint32_t)((vrow + 16*i)*144 + vchk*16),
                           Vtg + (size_t)(vrow + 16*i)*S_ + kvo + vchk*8);
        }
        CP_COMMIT();
        CP_WAIT1();
        __syncthreads();

        const __half* Kt = (const __half*)(fsm + (kt & 1)*FKSTG_B);
        const __half* Vt = (const __half*)(fsm + 2*FKSTG_B + (kt & 1)*FVSTG_B);

        // ---- scores ----
        float sc[8][4];
        #pragma unroll
        for (int j = 0; j < 8; j++)
            #pragma unroll
            for (int r = 0; r < 4; r++) sc[j][r] = 0.f;
        #pragma unroll
        for (int ks = 0; ks < 8; ks++) {
            const int kc = ks*16 + tr*2;
            #pragma unroll
            for (int j = 0; j < 8; j++) {
                const __half* kp = Kt + (j*8 + gq)*FKROW_H + kc;
                const uint32_t b0 = *(const uint32_t*)(kp);
                const uint32_t b1 = *(const uint32_t*)(kp + 8);
                mma_f16(sc[j][0], sc[j][1], sc[j][2], sc[j][3],
                        qa[ks][0], qa[ks][1], qa[ks][2], qa[ks][3], b0, b1);
            }
        }

        // ---- mask + row max ----
        const int mc = kt*64 + tr*2;
        float mx0 = -1e30f, mx1 = -1e30f;
        #pragma unroll
        for (int j = 0; j < 8; j++) {
            int2 mA = *(const int2*)(mask + mrow0 + mc + j*8);
            int2 mB = *(const int2*)(mask + mrow1 + mc + j*8);
            if (mA.x == 0) sc[j][0] = -10000.f;
            if (mA.y == 0) sc[j][1] = -10000.f;
            if (mB.x == 0) sc[j][2] = -10000.f;
            if (mB.y == 0) sc[j][3] = -10000.f;
            mx0 = fmaxf(mx0, fmaxf(sc[j][0], sc[j][1]));
            mx1 = fmaxf(mx1, fmaxf(sc[j][2], sc[j][3]));
        }
        mx0 = fmaxf(mx0, __shfl_xor_sync(0xffffffffu, mx0, 1));
        mx0 = fmaxf(mx0, __shfl_xor_sync(0xffffffffu, mx0, 2));
        mx1 = fmaxf(mx1, __shfl_xor_sync(0xffffffffu, mx1, 1));
        mx1 = fmaxf(mx1, __shfl_xor_sync(0xffffffffu, mx1, 2));

        const float mn0 = fmaxf(m0, mx0), mn1 = fmaxf(m1, mx1);
        const float f0 = __expf(m0 - mn0), f1 = __expf(m1 - mn1);
        m0 = mn0; m1 = mn1;

        float s0 = 0.f, s1 = 0.f;
        #pragma unroll
        for (int j = 0; j < 8; j++) {
            sc[j][0] = __expf(sc[j][0] - mn0); s0 += sc[j][0];
            sc[j][1] = __expf(sc[j][1] - mn0); s0 += sc[j][1];
            sc[j][2] = __expf(sc[j][2] - mn1); s1 += sc[j][2];
            sc[j][3] = __expf(sc[j][3] - mn1); s1 += sc[j][3];
        }
        s0 += __shfl_xor_sync(0xffffffffu, s0, 1);
        s0 += __shfl_xor_sync(0xffffffffu, s0, 2);
        s1 += __shfl_xor_sync(0xffffffffu, s1, 1);
        s1 += __shfl_xor_sync(0xffffffffu, s1, 2);
        l0 = l0 * f0 + s0;
        l1 = l1 * f1 + s1;

        #pragma unroll
        for (int jf = 0; jf < 16; jf++) {
            oc[jf][0] *= f0; oc[jf][1] *= f0;
            oc[jf][2] *= f1; oc[jf][3] *= f1;
        }

        // ---- PV ----
        #pragma unroll
        for (int ks = 0; ks < 4; ks++) {
            const uint32_t a0 = pack_h2(sc[2*ks][0],   sc[2*ks][1]);
            const uint32_t a1 = pack_h2(sc[2*ks][2],   sc[2*ks][3]);
            const uint32_t a2 = pack_h2(sc[2*ks+1][0], sc[2*ks+1][1]);
            const uint32_t a3 = pack_h2(sc[2*ks+1][2], sc[2*ks+1][3]);
            const int kc = ks*16 + tr*2;
            #pragma unroll
            for (int jf = 0; jf < 16; jf++) {
                const __half* vp = Vt + (jf*8 + gq)*FVROW_H + kc;
                const uint32_t b0 = *(const uint32_t*)(vp);
                const uint32_t b1 = *(const uint32_t*)(vp + 8);
                mma_f16(oc[jf][0], oc[jf][1], oc[jf][2], oc[jf][3],
                        a0, a1, a2, a3, b0, b1);
            }
        }
    }

    // ---- epilogue ----
    const float inv0 = 1.f / l0, inv1 = 1.f / l1;
    __half* O0 = O + ((size_t)(b*S_ + q0 + w*16 + gq)) * E_ + h*HD_;
    __half* O1 = O0 + (size_t)8 * E_;
    #pragma unroll
    for (int jf = 0; jf < 16; jf++) {
        const int c = jf*8 + tr*2;
        *(uint32_t*)(O0 + c) = pack_h2(oc[jf][0]*inv0, oc[jf][1]*inv0);
        *(uint32_t*)(O1 + c) = pack_h2(oc[jf][2]*inv1, oc[jf][3]*inv1);
    }
}

// ---------------------------------------------------------------------------
extern "C" void kernel_launch(void* const* d_in, const int* in_sizes, int n_in,
                              void* d_out, int out_size) {
    const float* x  = (const float*)d_in[0];
    const int* mask = (const int*)  d_in[1];
    const float* Wq = (const float*)d_in[2];
    const float* bq = (const float*)d_in[3];
    const float* Wk = (const float*)d_in[4];
    const float* bk = (const float*)d_in[5];
    const float* Wv = (const float*)d_in[6];
    const float* bv = (const float*)d_in[7];
    const float* Wo = (const float*)d_in[8];
    const float* bo = (const float*)d_in[9];
    float* out = (float*)d_out;

    __half *Qd,*Kd,*Vd,*Vtd,*Od,*Xr,*WqT,*WkT,*WvT,*WoT;
    cudaGetSymbolAddress((void**)&Qd,  g_Q);
    cudaGetSymbolAddress((void**)&Kd,  g_K);
    cudaGetSymbolAddress((void**)&Vd,  g_V);
    cudaGetSymbolAddress((void**)&Vtd, g_Vt);
    cudaGetSymbolAddress((void**)&Od,  g_O);
    cudaGetSymbolAddress((void**)&Xr,  g_Xr);
    cudaGetSymbolAddress((void**)&WqT, g_WqT);
    cudaGetSymbolAddress((void**)&WkT, g_WkT);
    cudaGetSymbolAddress((void**)&WvT, g_WvT);
    cudaGetSymbolAddress((void**)&WoT, g_WoT);

    cudaFuncSetAttribute(flash_h,   cudaFuncAttributeMaxDynamicSharedMemorySize, FLASH_SMEM);
    cudaFuncSetAttribute(gemm_h<0>, cudaFuncAttributeMaxDynamicSharedMemorySize, GEMM_SMEM);
    cudaFuncSetAttribute(gemm_h<1>, cudaFuncAttributeMaxDynamicSharedMemorySize, GEMM_SMEM);

    // prep
    f2h_copy<<<(MTOT*E_/2 + 255)/256, 256>>>(x, Xr, MTOT*E_/2);
    transpose_h<<<dim3(E_/32,  E_/32), dim3(32,8)>>>(Wq, WqT, E_, E_);
    transpose_h<<<dim3(GD_/32, E_/32), dim3(32,8)>>>(Wk, WkT, E_, GD_);
    transpose_h<<<dim3(GD_/32, E_/32), dim3(32,8)>>>(Wv, WvT, E_, GD_);
    transpose_h<<<dim3(E_/32,  E_/32), dim3(32,8)>>>(Wo, WoT, E_, E_);

    // projections
    gemm_h<1><<<dim3(E_/128,  MTOT/128), 256, GEMM_SMEM>>>(Xr, WqT, bq, Qd, E_,  E_);
    gemm_h<1><<<dim3(GD_/128, MTOT/128), 256, GEMM_SMEM>>>(Xr, WkT, bk, Kd, GD_, E_);
    gemm_h<1><<<dim3(GD_/128, MTOT/128), 256, GEMM_SMEM>>>(Xr, WvT, bv, Vd, GD_, E_);

    // V transpose
    vtrans_h<<<dim3(S_/32, HD_/32, B_*G_), dim3(32,8)>>>(Vd, Vtd);

    // attention: 64 q-rows per 128-thread CTA -> 2 CTAs/SM
    flash_h<<<dim3(S_/64, H_, B_), 128, FLASH_SMEM>>>(mask, Od);

    // output projection
    gemm_h<0><<<dim3(E_/128, MTOT/128), 256, GEMM_SMEM>>>(Od, WoT, bo, out, E_, E_);
}

// round 9
// speedup vs baseline: 9.2299x; 1.0175x over previous
#include <cuda_runtime.h>
#include <cuda_fp16.h>
#include <math.h>
#include <stdint.h>

#define B_  2
#define S_  2048
#define E_  2048
#define H_  16
#define G_  4
#define HD_ 128
#define GD_ 512
#define MTOT (B_*S_)

// ---------------- device scratch (allocation-free rule) ----------------
__device__ __half g_Q [(size_t)B_*H_*S_*HD_];   // [b][h][s][d]
__device__ __half g_K [(size_t)B_*G_*S_*HD_];   // [b][g][s][d]
__device__ __half g_Vt[(size_t)B_*G_*HD_*S_];   // [b][g][d][s]
__device__ __half g_O [(size_t)B_*S_*E_];       // attn out
__device__ __half g_Xr[(size_t)B_*S_*E_];       // x in fp16
__device__ __half g_WqT[(size_t)E_*E_];         // W^T [N][K] fp16
__device__ __half g_WkT[(size_t)GD_*E_];
__device__ __half g_WvT[(size_t)GD_*E_];
__device__ __half g_WoT[(size_t)E_*E_];
__device__ unsigned long long g_MB[(size_t)B_*S_*32];  // mask bits: 2048 bits/row

// ---------------- helpers ----------------
__device__ __forceinline__ uint32_t smem_u32(const void* p) {
    uint32_t a;
    asm("{ .reg .u64 t; cvta.to.shared.u64 t, %1; cvt.u32.u64 %0, t; }" : "=r"(a) : "l"(p));
    return a;
}
__device__ __forceinline__ uint32_t pack_h2(float lo, float hi) {
    __half2 v = __floats2half2_rn(lo, hi);
    return *reinterpret_cast<uint32_t*>(&v);
}

#define CP_ASYNC16(dst, src) \
    asm volatile("cp.async.cg.shared.global [%0], [%1], 16;" :: "r"(dst), "l"(src) : "memory")
#define CP_COMMIT() asm volatile("cp.async.commit_group;" ::: "memory")
#define CP_WAIT1()  asm volatile("cp.async.wait_group 1;"  ::: "memory")

__device__ __forceinline__ void mma_f16(float& d0, float& d1, float& d2, float& d3,
                                        uint32_t a0, uint32_t a1, uint32_t a2, uint32_t a3,
                                        uint32_t b0, uint32_t b1) {
    asm volatile("mma.sync.aligned.m16n8k16.row.col.f32.f16.f16.f32 "
                 "{%0,%1,%2,%3},{%4,%5,%6,%7},{%8,%9},{%0,%1,%2,%3};"
                 : "+f"(d0), "+f"(d1), "+f"(d2), "+f"(d3)
                 : "r"(a0), "r"(a1), "r"(a2), "r"(a3), "r"(b0), "r"(b1));
}

// ---------------------------------------------------------------------------
// Prep kernels (correctly sized)
// ---------------------------------------------------------------------------
__global__ void prep_w(const float* __restrict__ Wq, const float* __restrict__ Wk,
                       const float* __restrict__ Wv, const float* __restrict__ Wo) {
    __shared__ float tt[32][33];
    const int z = blockIdx.z;
    const int tx = threadIdx.x, ty = threadIdx.y;
    const float* in; __half* out; int Cc;
    if      (z == 0) { in = Wq; out = g_WqT; Cc = E_;  }
    else if (z == 1) { in = Wk; out = g_WkT; Cc = GD_; }
    else if (z == 2) { in = Wv; out = g_WvT; Cc = GD_; }
    else             { in = Wo; out = g_WoT; Cc = E_;  }
    const int c0 = blockIdx.x * 32, r0 = blockIdx.y * 32;
    if (c0 >= Cc) return;
    #pragma unroll
    for (int i = ty; i < 32; i += 8)
        tt[i][tx] = in[(size_t)(r0 + i) * Cc + c0 + tx];
    __syncthreads();
    #pragma unroll
    for (int i = ty; i < 32; i += 8)
        out[(size_t)(c0 + i) * E_ + r0 + tx] = __float2half_rn(tt[tx][i]);
}

__global__ void f2h_copy(const float* __restrict__ in, __half* __restrict__ out) {
    const size_t i = (size_t)blockIdx.x * 256 + threadIdx.x;   // pair index
    float2 v = *(const float2*)(in + 2*i);
    *(uint32_t*)(out + 2*i) = pack_h2(v.x, v.y);
}

__global__ void mask_pack(const int* __restrict__ mask) {
    const size_t i = (size_t)blockIdx.x * 256 + threadIdx.x;   // int index
    const unsigned v = (mask[i] != 0) ? 1u : 0u;
    const unsigned bal = __ballot_sync(0xffffffffu, v);
    if ((threadIdx.x & 31) == 0)
        ((uint32_t*)g_MB)[i >> 5] = bal;
}

// ---------------------------------------------------------------------------
// Fused QKV GEMM (fp16 mma): one launch, 768 CTAs.
// blockIdx.x: 0-15 Q-tiles, 16-19 K-tiles, 20-23 V-tiles (written transposed).
// ---------------------------------------------------------------------------
#define GROW_H 72
#define GSTG_B (128*GROW_H*2)
#define GSTG_PAIR (2*GSTG_B)
#define GEMM_SMEM (3*GSTG_PAIR)      // 110592

__global__ __launch_bounds__(256, 2)
void qkv_gemm(const float* __restrict__ bq, const float* __restrict__ bk,
              const float* __restrict__ bv) {
    extern __shared__ __align__(16) unsigned char gsm[];
    const uint32_t smb = smem_u32(gsm);

    const int t    = threadIdx.x;
    const int lane = t & 31;
    const int wid  = t >> 5;
    const int wm   = wid & 3;
    const int wn   = wid >> 2;
    const int gq   = lane >> 2;
    const int tr   = lane & 3;
    const int bx = blockIdx.x;
    const int m0 = blockIdx.y * 128;

    const __half* Bw; const float* bias; int nt, heads, vmode;
    if (bx < 16)      { Bw = g_WqT; bias = bq; nt = bx;      heads = 16; vmode = 0; }
    else if (bx < 20) { Bw = g_WkT; bias = bk; nt = bx - 16; heads = 4;  vmode = 0; }
    else              { Bw = g_WvT; bias = bv; nt = bx - 20; heads = 4;  vmode = 1; }
    const int n0 = nt * 128;
    const int K = E_;

    const int row8 = t >> 3, chk = t & 7;
    const __half* Agr = g_Xr + (size_t)(m0 + row8) * K + chk*8;
    const __half* Bgr = Bw   + (size_t)(n0 + row8) * K + chk*8;
    const uint32_t dA = smb + (uint32_t)(row8*144 + chk*16);
    const uint32_t dB = dA + GSTG_B;

    float acc[2][8][4];
    #pragma unroll
    for (int i = 0; i < 2; i++)
        #pragma unroll
        for (int j = 0; j < 8; j++)
            #pragma unroll
            for (int r = 0; r < 4; r++) acc[i][j][r] = 0.f;

    const int KT = K >> 6;

    #pragma unroll
    for (int p = 0; p < 2; p++) {
        const int k0 = p * 64;
        #pragma unroll
        for (int i = 0; i < 4; i++) {
            CP_ASYNC16(dA + p*GSTG_PAIR + i*32*144, Agr + (size_t)(i*32)*K + k0);
            CP_ASYNC16(dB + p*GSTG_PAIR + i*32*144, Bgr + (size_t)(i*32)*K + k0);
        }
        CP_COMMIT();
    }

    int s = 0, sl = 2;
    for (int it = 0; it < KT; it++) {
        CP_WAIT1();
        __syncthreads();

        if (it + 2 < KT) {
            const int k0 = (it + 2) * 64;
            const uint32_t so = (uint32_t)(sl * GSTG_PAIR);
            #pragma unroll
            for (int i = 0; i < 4; i++) {
                CP_ASYNC16(dA + so + i*32*144, Agr + (size_t)(i*32)*K + k0);
                CP_ASYNC16(dB + so + i*32*144, Bgr + (size_t)(i*32)*K + k0);
            }
        }
        CP_COMMIT();

        const __half* sA = (const __half*)(gsm + s*GSTG_PAIR);
        const __half* sB = (const __half*)(gsm + s*GSTG_PAIR + GSTG_B);
        #pragma unroll
        for (int ks = 0; ks < 4; ks++) {
            const int kc = ks*16 + tr*2;
            uint32_t a[2][4];
            #pragma unroll
            for (int mf = 0; mf < 2; mf++) {
                const __half* p0 = sA + (wm*32 + mf*16 + gq)*GROW_H + kc;
                a[mf][0] = *(const uint32_t*)(p0);
                a[mf][1] = *(const uint32_t*)(p0 + 8*GROW_H);
                a[mf][2] = *(const uint32_t*)(p0 + 8);
                a[mf][3] = *(const uint32_t*)(p0 + 8*GROW_H + 8);
            }
            #pragma unroll
            for (int nf = 0; nf < 8; nf++) {
                const __half* p0 = sB + (wn*64 + nf*8 + gq)*GROW_H + kc;
                const uint32_t b0 = *(const uint32_t*)(p0);
                const uint32_t b1 = *(const uint32_t*)(p0 + 8);
                #pragma unroll
                for (int mf = 0; mf < 2; mf++)
                    mma_f16(acc[mf][nf][0], acc[mf][nf][1], acc[mf][nf][2], acc[mf][nf][3],
                            a[mf][0], a[mf][1], a[mf][2], a[mf][3], b0, b1);
            }
        }

        s = (s + 1 == 3) ? 0 : s + 1;
        sl = (sl + 1 == 3) ? 0 : sl + 1;
    }

    // epilogue: 128-row tile lies within one batch (S_ multiple of 128)
    #pragma unroll
    for (int mf = 0; mf < 2; mf++) {
        const int row0 = m0 + wm*32 + mf*16 + gq;
        const int bb = row0 / S_, ss = row0 % S_;
        #pragma unroll
        for (int nf = 0; nf < 8; nf++) {
            const int col = n0 + wn*64 + nf*8 + tr*2;
            const float b0 = bias[col], b1 = bias[col+1];
            const int dcol = col - n0;
            if (!vmode) {
                __half* C = (bx < 16) ? g_Q : g_K;
                __half* Cp0 = C + (((size_t)(bb*heads + nt))*S_ + ss)*HD_ + dcol;
                *(uint32_t*)Cp0           = pack_h2(acc[mf][nf][0] + b0, acc[mf][nf][1] + b1);
                *(uint32_t*)(Cp0 + 8*HD_) = pack_h2(acc[mf][nf][2] + b0, acc[mf][nf][3] + b1);
            } else {
                // V transposed: g_Vt[(bb*G+g)*HD + d][s]
                __half* base = g_Vt + (((size_t)(bb*G_ + nt))*HD_ + dcol)*S_ + ss;
                base[0]       = __float2half_rn(acc[mf][nf][0] + b0);
                base[S_]      = __float2half_rn(acc[mf][nf][1] + b1);
                base[8]       = __float2half_rn(acc[mf][nf][2] + b0);
                base[S_ + 8]  = __float2half_rn(acc[mf][nf][3] + b1);
            }
        }
    }
}

// ---------------------------------------------------------------------------
// O projection GEMM (fp16 mma, fp32 row-major out)
// ---------------------------------------------------------------------------
__global__ __launch_bounds__(256, 2)
void o_gemm(const __half* __restrict__ A, const __half* __restrict__ Bw,
            const float* __restrict__ bias, float* __restrict__ C) {
    extern __shared__ __align__(16) unsigned char gsm[];
    const uint32_t smb = smem_u32(gsm);
    const int N = E_, K = E_;

    const int t    = threadIdx.x;
    const int lane = t & 31;
    const int wid  = t >> 5;
    const int wm   = wid & 3;
    const int wn   = wid >> 2;
    const int gq   = lane >> 2;
    const int tr   = lane & 3;
    const int m0 = blockIdx.y * 128, n0 = blockIdx.x * 128;

    const int row8 = t >> 3, chk = t & 7;
    const __half* Agr = A  + (size_t)(m0 + row8) * K + chk*8;
    const __half* Bgr = Bw + (size_t)(n0 + row8) * K + chk*8;
    const uint32_t dA = smb + (uint32_t)(row8*144 + chk*16);
    const uint32_t dB = dA + GSTG_B;

    float acc[2][8][4];
    #pragma unroll
    for (int i = 0; i < 2; i++)
        #pragma unroll
        for (int j = 0; j < 8; j++)
            #pragma unroll
            for (int r = 0; r < 4; r++) acc[i][j][r] = 0.f;

    const int KT = K >> 6;

    #pragma unroll
    for (int p = 0; p < 2; p++) {
        const int k0 = p * 64;
        #pragma unroll
        for (int i = 0; i < 4; i++) {
            CP_ASYNC16(dA + p*GSTG_PAIR + i*32*144, Agr + (size_t)(i*32)*K + k0);
            CP_ASYNC16(dB + p*GSTG_PAIR + i*32*144, Bgr + (size_t)(i*32)*K + k0);
        }
        CP_COMMIT();
    }

    int s = 0, sl = 2;
    for (int it = 0; it < KT; it++) {
        CP_WAIT1();
        __syncthreads();

        if (it + 2 < KT) {
            const int k0 = (it + 2) * 64;
            const uint32_t so = (uint32_t)(sl * GSTG_PAIR);
            #pragma unroll
            for (int i = 0; i < 4; i++) {
                CP_ASYNC16(dA + so + i*32*144, Agr + (size_t)(i*32)*K + k0);
                CP_ASYNC16(dB + so + i*32*144, Bgr + (size_t)(i*32)*K + k0);
            }
        }
        CP_COMMIT();

        const __half* sA = (const __half*)(gsm + s*GSTG_PAIR);
        const __half* sB = (const __half*)(gsm + s*GSTG_PAIR + GSTG_B);
        #pragma unroll
        for (int ks = 0; ks < 4; ks++) {
            const int kc = ks*16 + tr*2;
            uint32_t a[2][4];
            #pragma unroll
            for (int mf = 0; mf < 2; mf++) {
                const __half* p0 = sA + (wm*32 + mf*16 + gq)*GROW_H + kc;
                a[mf][0] = *(const uint32_t*)(p0);
                a[mf][1] = *(const uint32_t*)(p0 + 8*GROW_H);
                a[mf][2] = *(const uint32_t*)(p0 + 8);
                a[mf][3] = *(const uint32_t*)(p0 + 8*GROW_H + 8);
            }
            #pragma unroll
            for (int nf = 0; nf < 8; nf++) {
                const __half* p0 = sB + (wn*64 + nf*8 + gq)*GROW_H + kc;
                const uint32_t b0 = *(const uint32_t*)(p0);
                const uint32_t b1 = *(const uint32_t*)(p0 + 8);
                #pragma unroll
                for (int mf = 0; mf < 2; mf++)
                    mma_f16(acc[mf][nf][0], acc[mf][nf][1], acc[mf][nf][2], acc[mf][nf][3],
                            a[mf][0], a[mf][1], a[mf][2], a[mf][3], b0, b1);
            }
        }

        s = (s + 1 == 3) ? 0 : s + 1;
        sl = (sl + 1 == 3) ? 0 : sl + 1;
    }

    #pragma unroll
    for (int mf = 0; mf < 2; mf++) {
        const int row0 = m0 + wm*32 + mf*16 + gq;
        #pragma unroll
        for (int nf = 0; nf < 8; nf++) {
            const int col = n0 + wn*64 + nf*8 + tr*2;
            const float b0 = bias[col], b1 = bias[col+1];
            float* Cp0 = C + (size_t)row0 * N + col;
            float* Cp1 = Cp0 + (size_t)8 * N;
            *(float2*)Cp0 = make_float2(acc[mf][nf][0] + b0, acc[mf][nf][1] + b1);
            *(float2*)Cp1 = make_float2(acc[mf][nf][2] + b0, acc[mf][nf][3] + b1);
        }
    }
}

// ---------------------------------------------------------------------------
// Flash attention fp16 mma — 128-thread CTA, 64 q-rows, bitmask masking.
// ---------------------------------------------------------------------------
#define FKROW_H 136
#define FVROW_H 72
#define FKSTG_B (64*FKROW_H*2)     // 17408
#define FVSTG_B (128*FVROW_H*2)    // 18432
#define FLASH_SMEM (2*FKSTG_B + 2*FVSTG_B)   // 71680

__global__ __launch_bounds__(128)
void flash_h(__half* __restrict__ O) {
    extern __shared__ __align__(16) unsigned char fsm[];
    const int t = threadIdx.x, lane = t & 31, w = t >> 5;
    const int gq = lane >> 2, tr = lane & 3;
    const int qt = blockIdx.x, h = blockIdx.y, b = blockIdx.z;
    const int g  = h % G_;
    const int q0 = qt * 64;

    const __half* Qg  = g_Q  + (((size_t)(b*H_ + h))*S_ + q0) * HD_;
    const __half* Kg  = g_K  + (((size_t)(b*G_ + g))*S_) * HD_;
    const __half* Vtg = g_Vt + (((size_t)(b*G_ + g))*HD_) * S_;

    const uint32_t uK = smem_u32(fsm);
    const uint32_t uV = uK + 2*FKSTG_B;

    const int krow = t >> 4, kchk = t & 15;
    const int vrow = t >> 3, vchk = t & 7;

    // ---- Q fragments ----
    const float scale = 0.08838834764831845f;
    const int qrow = w*16 + gq;
    uint32_t qa[8][4];
    #pragma unroll
    for (int ks = 0; ks < 8; ks++) {
        const int c = ks*16 + tr*2;
        #pragma unroll
        for (int r = 0; r < 4; r++) {
            const int rr = qrow + (r & 1)*8;
            const int cc = c + (r >> 1)*8;
            const uint32_t u = *(const uint32_t*)(Qg + (size_t)rr*HD_ + cc);
            const __half2 hv = *reinterpret_cast<const __half2*>(&u);
            const float2 f = __half22float2(hv);
            qa[ks][r] = pack_h2(f.x*scale, f.y*scale);
        }
    }

    float oc[16][4];
    #pragma unroll
    for (int jf = 0; jf < 16; jf++)
        #pragma unroll
        for (int r = 0; r < 4; r++) oc[jf][r] = 0.f;
    float m0 = -1e30f, m1 = -1e30f, l0 = 0.f, l1 = 0.f;

    #pragma unroll
    for (int i = 0; i < 8; i++)
        CP_ASYNC16(uK + (uint32_t)((krow + 8*i)*272 + kchk*16),
                   Kg + (size_t)(krow + 8*i)*HD_ + kchk*8);
    #pragma unroll
    for (int i = 0; i < 8; i++)
        CP_ASYNC16(uV + (uint32_t)((vrow + 16*i)*144 + vchk*16),
                   Vtg + (size_t)(vrow + 16*i)*S_ + vchk*8);
    CP_COMMIT();

    const unsigned long long* mrow0p = g_MB + ((size_t)(b*S_ + q0 + w*16 + gq)) * 32;
    const unsigned long long* mrow1p = mrow0p + 8*32;

    for (int kt = 0; kt < S_/64; kt++) {
        __syncthreads();
        if (kt + 1 < S_/64) {
            const uint32_t so = ((kt+1) & 1);
            const size_t kvo = (size_t)(kt+1) * 64;
            #pragma unroll
            for (int i = 0; i < 8; i++)
                CP_ASYNC16(uK + so*FKSTG_B + (uint32_t)((krow + 8*i)*272 + kchk*16),
                           Kg + (kvo + krow + 8*i)*HD_ + kchk*8);
            #pragma unroll
            for (int i = 0; i < 8; i++)
                CP_ASYNC16(uV + so*FVSTG_B + (uint32_t)((vrow + 16*i)*144 + vchk*16),
                           Vtg + (size_t)(vrow + 16*i)*S_ + kvo + vchk*8);
        }
        CP_COMMIT();
        CP_WAIT1();
        __syncthreads();

        const __half* Kt = (const __half*)(fsm + (kt & 1)*FKSTG_B);
        const __half* Vt = (const __half*)(fsm + 2*FKSTG_B + (kt & 1)*FVSTG_B);

        // ---- scores ----
        float sc[8][4];
        #pragma unroll
        for (int j = 0; j < 8; j++)
            #pragma unroll
            for (int r = 0; r < 4; r++) sc[j][r] = 0.f;
        #pragma unroll
        for (int ks = 0; ks < 8; ks++) {
            const int kc = ks*16 + tr*2;
            #pragma unroll
            for (int j = 0; j < 8; j++) {
                const __half* kp = Kt + (j*8 + gq)*FKROW_H + kc;
                const uint32_t b0 = *(const uint32_t*)(kp);
                const uint32_t b1 = *(const uint32_t*)(kp + 8);
                mma_f16(sc[j][0], sc[j][1], sc[j][2], sc[j][3],
                        qa[ks][0], qa[ks][1], qa[ks][2], qa[ks][3], b0, b1);
            }
        }

        // ---- mask (bitmask) + row max ----
        const unsigned long long mb0 = mrow0p[kt];
        const unsigned long long mb1 = mrow1p[kt];
        float mx0 = -1e30f, mx1 = -1e30f;
        #pragma unroll
        for (int j = 0; j < 8; j++) {
            const int pos = tr*2 + j*8;
            if (!((mb0 >> pos) & 1ULL))       sc[j][0] = -10000.f;
            if (!((mb0 >> (pos+1)) & 1ULL))   sc[j][1] = -10000.f;
            if (!((mb1 >> pos) & 1ULL))       sc[j][2] = -10000.f;
            if (!((mb1 >> (pos+1)) & 1ULL))   sc[j][3] = -10000.f;
            mx0 = fmaxf(mx0, fmaxf(sc[j][0], sc[j][1]));
            mx1 = fmaxf(mx1, fmaxf(sc[j][2], sc[j][3]));
        }
        mx0 = fmaxf(mx0, __shfl_xor_sync(0xffffffffu, mx0, 1));
        mx0 = fmaxf(mx0, __shfl_xor_sync(0xffffffffu, mx0, 2));
        mx1 = fmaxf(mx1, __shfl_xor_sync(0xffffffffu, mx1, 1));
        mx1 = fmaxf(mx1, __shfl_xor_sync(0xffffffffu, mx1, 2));

        const float mn0 = fmaxf(m0, mx0), mn1 = fmaxf(m1, mx1);
        const float f0 = __expf(m0 - mn0), f1 = __expf(m1 - mn1);
        m0 = mn0; m1 = mn1;

        float s0 = 0.f, s1 = 0.f;
        #pragma unroll
        for (int j = 0; j < 8; j++) {
            sc[j][0] = __expf(sc[j][0] - mn0); s0 += sc[j][0];
            sc[j][1] = __expf(sc[j][1] - mn0); s0 += sc[j][1];
            sc[j][2] = __expf(sc[j][2] - mn1); s1 += sc[j][2];
            sc[j][3] = __expf(sc[j][3] - mn1); s1 += sc[j][3];
        }
        s0 += __shfl_xor_sync(0xffffffffu, s0, 1);
        s0 += __shfl_xor_sync(0xffffffffu, s0, 2);
        s1 += __shfl_xor_sync(0xffffffffu, s1, 1);
        s1 += __shfl_xor_sync(0xffffffffu, s1, 2);
        l0 = l0 * f0 + s0;
        l1 = l1 * f1 + s1;

        #pragma unroll
        for (int jf = 0; jf < 16; jf++) {
            oc[jf][0] *= f0; oc[jf][1] *= f0;
            oc[jf][2] *= f1; oc[jf][3] *= f1;
        }

        // ---- PV ----
        #pragma unroll
        for (int ks = 0; ks < 4; ks++) {
            const uint32_t a0 = pack_h2(sc[2*ks][0],   sc[2*ks][1]);
            const uint32_t a1 = pack_h2(sc[2*ks][2],   sc[2*ks][3]);
            const uint32_t a2 = pack_h2(sc[2*ks+1][0], sc[2*ks+1][1]);
            const uint32_t a3 = pack_h2(sc[2*ks+1][2], sc[2*ks+1][3]);
            const int kc = ks*16 + tr*2;
            #pragma unroll
            for (int jf = 0; jf < 16; jf++) {
                const __half* vp = Vt + (jf*8 + gq)*FVROW_H + kc;
                const uint32_t b0 = *(const uint32_t*)(vp);
                const uint32_t b1 = *(const uint32_t*)(vp + 8);
                mma_f16(oc[jf][0], oc[jf][1], oc[jf][2], oc[jf][3],
                        a0, a1, a2, a3, b0, b1);
            }
        }
    }

    // ---- epilogue ----
    const float inv0 = 1.f / l0, inv1 = 1.f / l1;
    __half* O0 = O + ((size_t)(b*S_ + q0 + w*16 + gq)) * E_ + h*HD_;
    __half* O1 = O0 + (size_t)8 * E_;
    #pragma unroll
    for (int jf = 0; jf < 16; jf++) {
        const int c = jf*8 + tr*2;
        *(uint32_t*)(O0 + c) = pack_h2(oc[jf][0]*inv0, oc[jf][1]*inv0);
        *(uint32_t*)(O1 + c) = pack_h2(oc[jf][2]*inv1, oc[jf][3]*inv1);
    }
}

// ---------------------------------------------------------------------------
extern "C" void kernel_launch(void* const* d_in, const int* in_sizes, int n_in,
                              void* d_out, int out_size) {
    const float* x  = (const float*)d_in[0];
    const int* mask = (const int*)  d_in[1];
    const float* Wq = (const float*)d_in[2];
    const float* bq = (const float*)d_in[3];
    const float* Wk = (const float*)d_in[4];
    const float* bk = (const float*)d_in[5];
    const float* Wv = (const float*)d_in[6];
    const float* bv = (const float*)d_in[7];
    const float* Wo = (const float*)d_in[8];
    const float* bo = (const float*)d_in[9];
    float* out = (float*)d_out;

    __half *Od, *WoT, *Xr;
    cudaGetSymbolAddress((void**)&Od,  g_O);
    cudaGetSymbolAddress((void**)&WoT, g_WoT);
    cudaGetSymbolAddress((void**)&Xr,  g_Xr);

    cudaFuncSetAttribute(flash_h,  cudaFuncAttributeMaxDynamicSharedMemorySize, FLASH_SMEM);
    cudaFuncSetAttribute(qkv_gemm, cudaFuncAttributeMaxDynamicSharedMemorySize, GEMM_SMEM);
    cudaFuncSetAttribute(o_gemm,   cudaFuncAttributeMaxDynamicSharedMemorySize, GEMM_SMEM);

    // prep (correctly sized)
    prep_w<<<dim3(64, 64, 4), dim3(32, 8)>>>(Wq, Wk, Wv, Wo);
    f2h_copy<<<MTOT*E_/2/256, 256>>>(x, Xr);
    mask_pack<<<(int)((size_t)B_*S_*S_/256), 256>>>(mask);

    // fused Q/K/V projections (V written transposed)
    qkv_gemm<<<dim3(24, MTOT/128), 256, GEMM_SMEM>>>(bq, bk, bv);

    // attention
    flash_h<<<dim3(S_/64, H_, B_), 128, FLASH_SMEM>>>(Od);

    // output projection
    o_gemm<<<dim3(E_/128, MTOT/128), 256, GEMM_SMEM>>>(Od, WoT, bo, out);
}

// round 10
// speedup vs baseline: 10.0082x; 1.0843x over previous
#include <cuda_runtime.h>
#include <cuda_fp16.h>
#include <math.h>
#include <stdint.h>

#define B_  2
#define S_  2048
#define E_  2048
#define H_  16
#define G_  4
#define HD_ 128
#define GD_ 512
#define MTOT (B_*S_)

// ---------------- device scratch (allocation-free rule) ----------------
__device__ __half g_Q [(size_t)B_*H_*S_*HD_];   // [b][h][s][d]
__device__ __half g_K [(size_t)B_*G_*S_*HD_];   // [b][g][s][d]
__device__ __half g_Vt[(size_t)B_*G_*HD_*S_];   // [b][g][d][s]
__device__ __half g_O [(size_t)B_*S_*E_];       // attn out
__device__ __half g_Xr[(size_t)B_*S_*E_];       // x in fp16
__device__ __half g_WqT[(size_t)E_*E_];         // W^T [N][K] fp16
__device__ __half g_WkT[(size_t)GD_*E_];
__device__ __half g_WvT[(size_t)GD_*E_];
__device__ __half g_WoT[(size_t)E_*E_];
__device__ unsigned long long g_MB[(size_t)B_*S_*32];  // mask bits: 2048 bits/row

// ---------------- helpers ----------------
__device__ __forceinline__ uint32_t smem_u32(const void* p) {
    uint32_t a;
    asm("{ .reg .u64 t; cvta.to.shared.u64 t, %1; cvt.u32.u64 %0, t; }" : "=r"(a) : "l"(p));
    return a;
}
__device__ __forceinline__ uint32_t pack_h2(float lo, float hi) {
    __half2 v = __floats2half2_rn(lo, hi);
    return *reinterpret_cast<uint32_t*>(&v);
}

#define CP_ASYNC16(dst, src) \
    asm volatile("cp.async.cg.shared.global [%0], [%1], 16;" :: "r"(dst), "l"(src) : "memory")
#define CP_COMMIT() asm volatile("cp.async.commit_group;" ::: "memory")
#define CP_WAIT1()  asm volatile("cp.async.wait_group 1;"  ::: "memory")

__device__ __forceinline__ void mma_f16(float& d0, float& d1, float& d2, float& d3,
                                        uint32_t a0, uint32_t a1, uint32_t a2, uint32_t a3,
                                        uint32_t b0, uint32_t b1) {
    asm volatile("mma.sync.aligned.m16n8k16.row.col.f32.f16.f16.f32 "
                 "{%0,%1,%2,%3},{%4,%5,%6,%7},{%8,%9},{%0,%1,%2,%3};"
                 : "+f"(d0), "+f"(d1), "+f"(d2), "+f"(d3)
                 : "r"(a0), "r"(a1), "r"(a2), "r"(a3), "r"(b0), "r"(b1));
}
__device__ __forceinline__ void ldsm_x4(uint32_t& r0, uint32_t& r1, uint32_t& r2, uint32_t& r3,
                                        uint32_t addr) {
    asm volatile("ldmatrix.sync.aligned.m8n8.x4.shared.b16 {%0,%1,%2,%3}, [%4];"
                 : "=r"(r0), "=r"(r1), "=r"(r2), "=r"(r3) : "r"(addr));
}

// ---------------------------------------------------------------------------
// Prep kernels
// ---------------------------------------------------------------------------
__global__ void prep_w(const float* __restrict__ Wq, const float* __restrict__ Wk,
                       const float* __restrict__ Wv, const float* __restrict__ Wo) {
    __shared__ float tt[32][33];
    const int z = blockIdx.z;
    const int tx = threadIdx.x, ty = threadIdx.y;
    const float* in; __half* out; int Cc;
    if      (z == 0) { in = Wq; out = g_WqT; Cc = E_;  }
    else if (z == 1) { in = Wk; out = g_WkT; Cc = GD_; }
    else if (z == 2) { in = Wv; out = g_WvT; Cc = GD_; }
    else             { in = Wo; out = g_WoT; Cc = E_;  }
    const int c0 = blockIdx.x * 32, r0 = blockIdx.y * 32;
    if (c0 >= Cc) return;
    #pragma unroll
    for (int i = ty; i < 32; i += 8)
        tt[i][tx] = in[(size_t)(r0 + i) * Cc + c0 + tx];
    __syncthreads();
    #pragma unroll
    for (int i = ty; i < 32; i += 8)
        out[(size_t)(c0 + i) * E_ + r0 + tx] = __float2half_rn(tt[tx][i]);
}

__global__ void f2h_copy(const float* __restrict__ in, __half* __restrict__ out) {
    const size_t i = (size_t)blockIdx.x * 256 + threadIdx.x;   // pair index
    float2 v = *(const float2*)(in + 2*i);
    *(uint32_t*)(out + 2*i) = pack_h2(v.x, v.y);
}

__global__ void mask_pack(const int* __restrict__ mask) {
    const size_t i = (size_t)blockIdx.x * 256 + threadIdx.x;   // int index
    const unsigned v = (mask[i] != 0) ? 1u : 0u;
    const unsigned bal = __ballot_sync(0xffffffffu, v);
    if ((threadIdx.x & 31) == 0)
        ((uint32_t*)g_MB)[i >> 5] = bal;
}

// ---------------------------------------------------------------------------
// Fused QKV GEMM (fp16 mma + ldmatrix): one launch, 768 CTAs.
// ---------------------------------------------------------------------------
#define GROW_H 72
#define GROWB  144                   // bytes per SMEM row
#define GSTG_B (128*GROW_H*2)
#define GSTG_PAIR (2*GSTG_B)
#define GEMM_SMEM (3*GSTG_PAIR)      // 110592

__global__ __launch_bounds__(256, 2)
void qkv_gemm(const float* __restrict__ bq, const float* __restrict__ bk,
              const float* __restrict__ bv) {
    extern __shared__ __align__(16) unsigned char gsm[];
    const uint32_t smb = smem_u32(gsm);

    const int t    = threadIdx.x;
    const int lane = t & 31;
    const int wid  = t >> 5;
    const int wm   = wid & 3;
    const int wn   = wid >> 2;
    const int gq   = lane >> 2;
    const int tr   = lane & 3;
    const int lrow = lane & 7, lmat = lane >> 3;
    const int bx = blockIdx.x;
    const int m0 = blockIdx.y * 128;

    const __half* Bw; const float* bias; int nt, heads, vmode;
    if (bx < 16)      { Bw = g_WqT; bias = bq; nt = bx;      heads = 16; vmode = 0; }
    else if (bx < 20) { Bw = g_WkT; bias = bk; nt = bx - 16; heads = 4;  vmode = 0; }
    else              { Bw = g_WvT; bias = bv; nt = bx - 20; heads = 4;  vmode = 1; }
    const int n0 = nt * 128;
    const int K = E_;

    const int row8 = t >> 3, chk = t & 7;
    const __half* Agr = g_Xr + (size_t)(m0 + row8) * K + chk*8;
    const __half* Bgr = Bw   + (size_t)(n0 + row8) * K + chk*8;
    const uint32_t dA = smb + (uint32_t)(row8*GROWB + chk*16);
    const uint32_t dB = dA + GSTG_B;

    // ldmatrix lane offsets (bytes, within a stage)
    const uint32_t aoff = (uint32_t)(((wm*32 + (lmat&1)*8 + lrow)*GROW_H + (lmat>>1)*8) * 2);
    const uint32_t boff = (uint32_t)(((wn*64 + (lmat>>1)*8 + lrow)*GROW_H + (lmat&1)*8) * 2) + GSTG_B;

    float acc[2][8][4];
    #pragma unroll
    for (int i = 0; i < 2; i++)
        #pragma unroll
        for (int j = 0; j < 8; j++)
            #pragma unroll
            for (int r = 0; r < 4; r++) acc[i][j][r] = 0.f;

    const int KT = K >> 6;

    #pragma unroll
    for (int p = 0; p < 2; p++) {
        const int k0 = p * 64;
        #pragma unroll
        for (int i = 0; i < 4; i++) {
            CP_ASYNC16(dA + p*GSTG_PAIR + i*32*GROWB, Agr + (size_t)(i*32)*K + k0);
            CP_ASYNC16(dB + p*GSTG_PAIR + i*32*GROWB, Bgr + (size_t)(i*32)*K + k0);
        }
        CP_COMMIT();
    }

    int s = 0, sl = 2;
    for (int it = 0; it < KT; it++) {
        CP_WAIT1();
        __syncthreads();

        if (it + 2 < KT) {
            const int k0 = (it + 2) * 64;
            const uint32_t so = (uint32_t)(sl * GSTG_PAIR);
            #pragma unroll
            for (int i = 0; i < 4; i++) {
                CP_ASYNC16(dA + so + i*32*GROWB, Agr + (size_t)(i*32)*K + k0);
                CP_ASYNC16(dB + so + i*32*GROWB, Bgr + (size_t)(i*32)*K + k0);
            }
        }
        CP_COMMIT();

        const uint32_t sbase = smb + (uint32_t)(s * GSTG_PAIR);
        #pragma unroll
        for (int ks = 0; ks < 4; ks++) {
            uint32_t a[2][4];
            #pragma unroll
            for (int mf = 0; mf < 2; mf++)
                ldsm_x4(a[mf][0], a[mf][1], a[mf][2], a[mf][3],
                        sbase + aoff + mf*(16*GROWB) + ks*32);
            #pragma unroll
            for (int p = 0; p < 4; p++) {
                uint32_t b0, b1, b2, b3;
                ldsm_x4(b0, b1, b2, b3, sbase + boff + p*(16*GROWB) + ks*32);
                #pragma unroll
                for (int mf = 0; mf < 2; mf++) {
                    mma_f16(acc[mf][2*p][0], acc[mf][2*p][1], acc[mf][2*p][2], acc[mf][2*p][3],
                            a[mf][0], a[mf][1], a[mf][2], a[mf][3], b0, b1);
                    mma_f16(acc[mf][2*p+1][0], acc[mf][2*p+1][1], acc[mf][2*p+1][2], acc[mf][2*p+1][3],
                            a[mf][0], a[mf][1], a[mf][2], a[mf][3], b2, b3);
                }
            }
        }

        s = (s + 1 == 3) ? 0 : s + 1;
        sl = (sl + 1 == 3) ? 0 : sl + 1;
    }

    // epilogue: 128-row tile lies within one batch
    #pragma unroll
    for (int mf = 0; mf < 2; mf++) {
        const int row0 = m0 + wm*32 + mf*16 + gq;
        const int bb = row0 / S_, ss = row0 % S_;
        #pragma unroll
        for (int nf = 0; nf < 8; nf++) {
            const int col = n0 + wn*64 + nf*8 + tr*2;
            const float b0 = bias[col], b1 = bias[col+1];
            const int dcol = col - n0;
            if (!vmode) {
                __half* C = (bx < 16) ? g_Q : g_K;
                __half* Cp0 = C + (((size_t)(bb*heads + nt))*S_ + ss)*HD_ + dcol;
                *(uint32_t*)Cp0           = pack_h2(acc[mf][nf][0] + b0, acc[mf][nf][1] + b1);
                *(uint32_t*)(Cp0 + 8*HD_) = pack_h2(acc[mf][nf][2] + b0, acc[mf][nf][3] + b1);
            } else {
                __half* base = g_Vt + (((size_t)(bb*G_ + nt))*HD_ + dcol)*S_ + ss;
                base[0]       = __float2half_rn(acc[mf][nf][0] + b0);
                base[S_]      = __float2half_rn(acc[mf][nf][1] + b1);
                base[8]       = __float2half_rn(acc[mf][nf][2] + b0);
                base[S_ + 8]  = __float2half_rn(acc[mf][nf][3] + b1);
            }
        }
    }
}

// ---------------------------------------------------------------------------
// O projection GEMM (fp16 mma + ldmatrix, fp32 row-major out)
// ---------------------------------------------------------------------------
__global__ __launch_bounds__(256, 2)
void o_gemm(const __half* __restrict__ A, const __half* __restrict__ Bw,
            const float* __restrict__ bias, float* __restrict__ C) {
    extern __shared__ __align__(16) unsigned char gsm[];
    const uint32_t smb = smem_u32(gsm);
    const int N = E_, K = E_;

    const int t    = threadIdx.x;
    const int lane = t & 31;
    const int wid  = t >> 5;
    const int wm   = wid & 3;
    const int wn   = wid >> 2;
    const int gq   = lane >> 2;
    const int tr   = lane & 3;
    const int lrow = lane & 7, lmat = lane >> 3;
    const int m0 = blockIdx.y * 128, n0 = blockIdx.x * 128;

    const int row8 = t >> 3, chk = t & 7;
    const __half* Agr = A  + (size_t)(m0 + row8) * K + chk*8;
    const __half* Bgr = Bw + (size_t)(n0 + row8) * K + chk*8;
    const uint32_t dA = smb + (uint32_t)(row8*GROWB + chk*16);
    const uint32_t dB = dA + GSTG_B;

    const uint32_t aoff = (uint32_t)(((wm*32 + (lmat&1)*8 + lrow)*GROW_H + (lmat>>1)*8) * 2);
    const uint32_t boff = (uint32_t)(((wn*64 + (lmat>>1)*8 + lrow)*GROW_H + (lmat&1)*8) * 2) + GSTG_B;

    float acc[2][8][4];
    #pragma unroll
    for (int i = 0; i < 2; i++)
        #pragma unroll
        for (int j = 0; j < 8; j++)
            #pragma unroll
            for (int r = 0; r < 4; r++) acc[i][j][r] = 0.f;

    const int KT = K >> 6;

    #pragma unroll
    for (int p = 0; p < 2; p++) {
        const int k0 = p * 64;
        #pragma unroll
        for (int i = 0; i < 4; i++) {
            CP_ASYNC16(dA + p*GSTG_PAIR + i*32*GROWB, Agr + (size_t)(i*32)*K + k0);
            CP_ASYNC16(dB + p*GSTG_PAIR + i*32*GROWB, Bgr + (size_t)(i*32)*K + k0);
        }
        CP_COMMIT();
    }

    int s = 0, sl = 2;
    for (int it = 0; it < KT; it++) {
        CP_WAIT1();
        __syncthreads();

        if (it + 2 < KT) {
            const int k0 = (it + 2) * 64;
            const uint32_t so = (uint32_t)(sl * GSTG_PAIR);
            #pragma unroll
            for (int i = 0; i < 4; i++) {
                CP_ASYNC16(dA + so + i*32*GROWB, Agr + (size_t)(i*32)*K + k0);
                CP_ASYNC16(dB + so + i*32*GROWB, Bgr + (size_t)(i*32)*K + k0);
            }
        }
        CP_COMMIT();

        const uint32_t sbase = smb + (uint32_t)(s * GSTG_PAIR);
        #pragma unroll
        for (int ks = 0; ks < 4; ks++) {
            uint32_t a[2][4];
            #pragma unroll
            for (int mf = 0; mf < 2; mf++)
                ldsm_x4(a[mf][0], a[mf][1], a[mf][2], a[mf][3],
                        sbase + aoff + mf*(16*GROWB) + ks*32);
            #pragma unroll
            for (int p = 0; p < 4; p++) {
                uint32_t b0, b1, b2, b3;
                ldsm_x4(b0, b1, b2, b3, sbase + boff + p*(16*GROWB) + ks*32);
                #pragma unroll
                for (int mf = 0; mf < 2; mf++) {
                    mma_f16(acc[mf][2*p][0], acc[mf][2*p][1], acc[mf][2*p][2], acc[mf][2*p][3],
                            a[mf][0], a[mf][1], a[mf][2], a[mf][3], b0, b1);
                    mma_f16(acc[mf][2*p+1][0], acc[mf][2*p+1][1], acc[mf][2*p+1][2], acc[mf][2*p+1][3],
                            a[mf][0], a[mf][1], a[mf][2], a[mf][3], b2, b3);
                }
            }
        }

        s = (s + 1 == 3) ? 0 : s + 1;
        sl = (sl + 1 == 3) ? 0 : sl + 1;
    }

    #pragma unroll
    for (int mf = 0; mf < 2; mf++) {
        const int row0 = m0 + wm*32 + mf*16 + gq;
        #pragma unroll
        for (int nf = 0; nf < 8; nf++) {
            const int col = n0 + wn*64 + nf*8 + tr*2;
            const float b0 = bias[col], b1 = bias[col+1];
            float* Cp0 = C + (size_t)row0 * N + col;
            float* Cp1 = Cp0 + (size_t)8 * N;
            *(float2*)Cp0 = make_float2(acc[mf][nf][0] + b0, acc[mf][nf][1] + b1);
            *(float2*)Cp1 = make_float2(acc[mf][nf][2] + b0, acc[mf][nf][3] + b1);
        }
    }
}

// ---------------------------------------------------------------------------
// Flash attention fp16 mma + ldmatrix — 128-thread CTA, 64 q-rows.
// ---------------------------------------------------------------------------
#define FKROW_H 136
#define FKROWB  272
#define FVROW_H 72
#define FVROWB  144
#define FKSTG_B (64*FKROWB)        // 17408
#define FVSTG_B (128*FVROWB)       // 18432
#define FLASH_SMEM (2*FKSTG_B + 2*FVSTG_B)   // 71680

__global__ __launch_bounds__(128)
void flash_h(__half* __restrict__ O) {
    extern __shared__ __align__(16) unsigned char fsm[];
    const int t = threadIdx.x, lane = t & 31, w = t >> 5;
    const int gq = lane >> 2, tr = lane & 3;
    const int lrow = lane & 7, lmat = lane >> 3;
    const int qt = blockIdx.x, h = blockIdx.y, b = blockIdx.z;
    const int g  = h % G_;
    const int q0 = qt * 64;

    const __half* Qg  = g_Q  + (((size_t)(b*H_ + h))*S_ + q0) * HD_;
    const __half* Kg  = g_K  + (((size_t)(b*G_ + g))*S_) * HD_;
    const __half* Vtg = g_Vt + (((size_t)(b*G_ + g))*HD_) * S_;

    const uint32_t uK = smem_u32(fsm);
    const uint32_t uV = uK + 2*FKSTG_B;

    const int krow = t >> 4, kchk = t & 15;
    const int vrow = t >> 3, vchk = t & 7;

    // ldmatrix lane offsets (bytes, within one stage)
    const uint32_t koff = (uint32_t)((((lmat>>1)*8 + lrow)*FKROW_H + (lmat&1)*8) * 2);
    const uint32_t voff = (uint32_t)((((lmat>>1)*8 + lrow)*FVROW_H + (lmat&1)*8) * 2);

    // ---- Q fragments ----
    const float scale = 0.08838834764831845f;
    const int qrow = w*16 + gq;
    uint32_t qa[8][4];
    #pragma unroll
    for (int ks = 0; ks < 8; ks++) {
        const int c = ks*16 + tr*2;
        #pragma unroll
        for (int r = 0; r < 4; r++) {
            const int rr = qrow + (r & 1)*8;
            const int cc = c + (r >> 1)*8;
            const uint32_t u = *(const uint32_t*)(Qg + (size_t)rr*HD_ + cc);
            const __half2 hv = *reinterpret_cast<const __half2*>(&u);
            const float2 f = __half22float2(hv);
            qa[ks][r] = pack_h2(f.x*scale, f.y*scale);
        }
    }

    float oc[16][4];
    #pragma unroll
    for (int jf = 0; jf < 16; jf++)
        #pragma unroll
        for (int r = 0; r < 4; r++) oc[jf][r] = 0.f;
    float m0 = -1e30f, m1 = -1e30f, l0 = 0.f, l1 = 0.f;

    #pragma unroll
    for (int i = 0; i < 8; i++)
        CP_ASYNC16(uK + (uint32_t)((krow + 8*i)*FKROWB + kchk*16),
                   Kg + (size_t)(krow + 8*i)*HD_ + kchk*8);
    #pragma unroll
    for (int i = 0; i < 8; i++)
        CP_ASYNC16(uV + (uint32_t)((vrow + 16*i)*FVROWB + vchk*16),
                   Vtg + (size_t)(vrow + 16*i)*S_ + vchk*8);
    CP_COMMIT();

    const unsigned long long* mrow0p = g_MB + ((size_t)(b*S_ + q0 + w*16 + gq)) * 32;
    const unsigned long long* mrow1p = mrow0p + 8*32;

    for (int kt = 0; kt < S_/64; kt++) {
        __syncthreads();
        if (kt + 1 < S_/64) {
            const uint32_t so = ((kt+1) & 1);
            const size_t kvo = (size_t)(kt+1) * 64;
            #pragma unroll
            for (int i = 0; i < 8; i++)
                CP_ASYNC16(uK + so*FKSTG_B + (uint32_t)((krow + 8*i)*FKROWB + kchk*16),
                           Kg + (kvo + krow + 8*i)*HD_ + kchk*8);
            #pragma unroll
            for (int i = 0; i < 8; i++)
                CP_ASYNC16(uV + so*FVSTG_B + (uint32_t)((vrow + 16*i)*FVROWB + vchk*16),
                           Vtg + (size_t)(vrow + 16*i)*S_ + kvo + vchk*8);
        }
        CP_COMMIT();
        CP_WAIT1();
        __syncthreads();

        const uint32_t uKst = uK + (kt & 1)*FKSTG_B;
        const uint32_t uVst = uV + (kt & 1)*FVSTG_B;

        // ---- scores ----
        float sc[8][4];
        #pragma unroll
        for (int j = 0; j < 8; j++)
            #pragma unroll
            for (int r = 0; r < 4; r++) sc[j][r] = 0.f;
        #pragma unroll
        for (int ks = 0; ks < 8; ks++) {
            #pragma unroll
            for (int p = 0; p < 4; p++) {
                uint32_t b0, b1, b2, b3;
                ldsm_x4(b0, b1, b2, b3, uKst + koff + p*(16*FKROWB) + ks*32);
                mma_f16(sc[2*p][0], sc[2*p][1], sc[2*p][2], sc[2*p][3],
                        qa[ks][0], qa[ks][1], qa[ks][2], qa[ks][3], b0, b1);
                mma_f16(sc[2*p+1][0], sc[2*p+1][1], sc[2*p+1][2], sc[2*p+1][3],
                        qa[ks][0], qa[ks][1], qa[ks][2], qa[ks][3], b2, b3);
            }
        }

        // ---- mask (bitmask) + row max ----
        const unsigned long long mb0 = mrow0p[kt];
        const unsigned long long mb1 = mrow1p[kt];
        float mx0 = -1e30f, mx1 = -1e30f;
        #pragma unroll
        for (int j = 0; j < 8; j++) {
            const int pos = tr*2 + j*8;
            if (!((mb0 >> pos) & 1ULL))       sc[j][0] = -10000.f;
            if (!((mb0 >> (pos+1)) & 1ULL))   sc[j][1] = -10000.f;
            if (!((mb1 >> pos) & 1ULL))       sc[j][2] = -10000.f;
            if (!((mb1 >> (pos+1)) & 1ULL))   sc[j][3] = -10000.f;
            mx0 = fmaxf(mx0, fmaxf(sc[j][0], sc[j][1]));
            mx1 = fmaxf(mx1, fmaxf(sc[j][2], sc[j][3]));
        }
        mx0 = fmaxf(mx0, __shfl_xor_sync(0xffffffffu, mx0, 1));
        mx0 = fmaxf(mx0, __shfl_xor_sync(0xffffffffu, mx0, 2));
        mx1 = fmaxf(mx1, __shfl_xor_sync(0xffffffffu, mx1, 1));
        mx1 = fmaxf(mx1, __shfl_xor_sync(0xffffffffu, mx1, 2));

        const float mn0 = fmaxf(m0, mx0), mn1 = fmaxf(m1, mx1);
        const float f0 = __expf(m0 - mn0), f1 = __expf(m1 - mn1);
        m0 = mn0; m1 = mn1;

        float s0 = 0.f, s1 = 0.f;
        #pragma unroll
        for (int j = 0; j < 8; j++) {
            sc[j][0] = __expf(sc[j][0] - mn0); s0 += sc[j][0];
            sc[j][1] = __expf(sc[j][1] - mn0); s0 += sc[j][1];
            sc[j][2] = __expf(sc[j][2] - mn1); s1 += sc[j][2];
            sc[j][3] = __expf(sc[j][3] - mn1); s1 += sc[j][3];
        }
        s0 += __shfl_xor_sync(0xffffffffu, s0, 1);
        s0 += __shfl_xor_sync(0xffffffffu, s0, 2);
        s1 += __shfl_xor_sync(0xffffffffu, s1, 1);
        s1 += __shfl_xor_sync(0xffffffffu, s1, 2);
        l0 = l0 * f0 + s0;
        l1 = l1 * f1 + s1;

        #pragma unroll
        for (int jf = 0; jf < 16; jf++) {
            oc[jf][0] *= f0; oc[jf][1] *= f0;
            oc[jf][2] *= f1; oc[jf][3] *= f1;
        }

        // ---- PV ----
        #pragma unroll
        for (int ks = 0; ks < 4; ks++) {
            const uint32_t a0 = pack_h2(sc[2*ks][0],   sc[2*ks][1]);
            const uint32_t a1 = pack_h2(sc[2*ks][2],   sc[2*ks][3]);
            const uint32_t a2 = pack_h2(sc[2*ks+1][0], sc[2*ks+1][1]);
            const uint32_t a3 = pack_h2(sc[2*ks+1][2], sc[2*ks+1][3]);
            #pragma unroll
            for (int p = 0; p < 8; p++) {
                uint32_t b0, b1, b2, b3;
                ldsm_x4(b0, b1, b2, b3, uVst + voff + p*(16*FVROWB) + ks*32);
                mma_f16(oc[2*p][0], oc[2*p][1], oc[2*p][2], oc[2*p][3],
                        a0, a1, a2, a3, b0, b1);
                mma_f16(oc[2*p+1][0], oc[2*p+1][1], oc[2*p+1][2], oc[2*p+1][3],
                        a0, a1, a2, a3, b2, b3);
            }
        }
    }

    // ---- epilogue ----
    const float inv0 = 1.f / l0, inv1 = 1.f / l1;
    __half* O0 = O + ((size_t)(b*S_ + q0 + w*16 + gq)) * E_ + h*HD_;
    __half* O1 = O0 + (size_t)8 * E_;
    #pragma unroll
    for (int jf = 0; jf < 16; jf++) {
        const int c = jf*8 + tr*2;
        *(uint32_t*)(O0 + c) = pack_h2(oc[jf][0]*inv0, oc[jf][1]*inv0);
        *(uint32_t*)(O1 + c) = pack_h2(oc[jf][2]*inv1, oc[jf][3]*inv1);
    }
}

// ---------------------------------------------------------------------------
extern "C" void kernel_launch(void* const* d_in, const int* in_sizes, int n_in,
                              void* d_out, int out_size) {
    const float* x  = (const float*)d_in[0];
    const int* mask = (const int*)  d_in[1];
    const float* Wq = (const float*)d_in[2];
    const float* bq = (const float*)d_in[3];
    const float* Wk = (const float*)d_in[4];
    const float* bk = (const float*)d_in[5];
    const float* Wv = (const float*)d_in[6];
    const float* bv = (const float*)d_in[7];
    const float* Wo = (const float*)d_in[8];
    const float* bo = (const float*)d_in[9];
    float* out = (float*)d_out;

    __half *Od, *WoT, *Xr;
    cudaGetSymbolAddress((void**)&Od,  g_O);
    cudaGetSymbolAddress((void**)&WoT, g_WoT);
    cudaGetSymbolAddress((void**)&Xr,  g_Xr);

    cudaFuncSetAttribute(flash_h,  cudaFuncAttributeMaxDynamicSharedMemorySize, FLASH_SMEM);
    cudaFuncSetAttribute(qkv_gemm, cudaFuncAttributeMaxDynamicSharedMemorySize, GEMM_SMEM);
    cudaFuncSetAttribute(o_gemm,   cudaFuncAttributeMaxDynamicSharedMemorySize, GEMM_SMEM);

    // prep
    prep_w<<<dim3(64, 64, 4), dim3(32, 8)>>>(Wq, Wk, Wv, Wo);
    f2h_copy<<<MTOT*E_/2/256, 256>>>(x, Xr);
    mask_pack<<<(int)((size_t)B_*S_*S_/256), 256>>>(mask);

    // fused Q/K/V projections (V written transposed)
    qkv_gemm<<<dim3(24, MTOT/128), 256, GEMM_SMEM>>>(bq, bk, bv);

    // attention
    flash_h<<<dim3(S_/64, H_, B_), 128, FLASH_SMEM>>>(Od);

    // output projection
    o_gemm<<<dim3(E_/128, MTOT/128), 256, GEMM_SMEM>>>(Od, WoT, bo, out);
}